// round 4
// baseline (speedup 1.0000x reference)
#include <cuda_runtime.h>
#include <math.h>

// Problem constants (fixed by setup_inputs)
#define B_    16
#define S_    2048
#define D_    1024
#define H_    16
#define P_    8
#define R_    64
#define NSUM  73                  // 1 cls + 8 pma + 64 recent
#define NROWS (B_*NSUM)           // 1168
#define MPAD  1280                // padded row count for stage-G GEMM
#define KSPLIT_POOL 4

// ---------------- scratch (device globals; zero-initialized at load) ----------------
__device__ float g_q[P_*D_];
__device__ float g_qt[128*D_];
__device__ float g_scores[(long)B_*128*S_];          // also holds attn after softmax
__device__ float g_Y[(long)B_*128*D_];
__device__ float g_ctx[(long)B_*P_*D_];
__device__ float g_pooled[(long)KSPLIT_POOL*B_*P_*D_]; // split-K partials (no atomics)
__device__ float g_summary[(long)NROWS*D_];
__device__ float g_norm[2L*MPAD*D_];                 // [0]=LN_v rows, [1]=LN_g rows; pad rows stay 0
__device__ float g_valgate[2L*MPAD*D_];              // [0]=val pre-act, [1]=gate pre-act
__device__ float g_maskf[NROWS];
__device__ int   g_len[B_];
__device__ int   g_mode;                             // 1 = int32 mask, 0 = uint8 mask

// ---------------- mask-encoding detection (reads first 16 bytes only; always safe) ----
__global__ void k_mode(const int* __restrict__ mask_as_int) {
    // bool->int32: words are 0 or 1. bool->uint8: words pack 4 bool bytes
    // (0x01010101-style patterns, or {257,65793} for short prefixes).
    int w0 = mask_as_int[0], w1 = mask_as_int[1], w2 = mask_as_int[2], w3 = mask_as_int[3];
    int is_i32 = ((unsigned)w0 <= 1u) & ((unsigned)w1 <= 1u) &
                 ((unsigned)w2 <= 1u) & ((unsigned)w3 <= 1u);
    g_mode = is_i32;
}

// ---------------- lengths from valid_mask (dtype-adaptive) ----------------
__global__ void k_len(const void* __restrict__ mask) {
    int b = blockIdx.x, t = threadIdx.x;
    int mode = g_mode;
    int s = 0;
    if (mode) {
        const int* m = (const int*)mask;
        for (int i = t; i < S_; i += 256) s += (m[(long)b*S_ + i] != 0) ? 1 : 0;
    } else {
        const unsigned char* m = (const unsigned char*)mask;
        for (int i = t; i < S_; i += 256) s += m[(long)b*S_ + i] ? 1 : 0;
    }
    __shared__ int sh[256];
    sh[t] = s; __syncthreads();
    for (int o = 128; o > 0; o >>= 1) { if (t < o) sh[t] += sh[t+o]; __syncthreads(); }
    if (t == 0) g_len[b] = sh[0];
}

// ---------------- q = queries @ Wq^T + bq  (warp per output) ----------------
__global__ void k_q(const float* __restrict__ queries, const float* __restrict__ W,
                    const float* __restrict__ bias) {
    int w = (blockIdx.x*blockDim.x + threadIdx.x) >> 5;
    int lane = threadIdx.x & 31;
    if (w >= P_*D_) return;
    int p = w / D_, d = w % D_;
    const float* qr = queries + (long)p*D_;
    const float* wr = W + (long)d*D_;
    float acc = 0.f;
    for (int k = lane; k < D_; k += 32) acc += qr[k]*wr[k];
    for (int o = 16; o > 0; o >>= 1) acc += __shfl_down_sync(0xffffffffu, acc, o);
    if (lane == 0) g_q[(long)p*D_ + d] = acc + bias[d];
}

// ---------------- qt[hp,d] = (1/8) * sum_j q[p, h*64+j] * Wk[h*64+j, d] ----------------
__global__ void k_qt(const float* __restrict__ W) {
    int idx = blockIdx.x*blockDim.x + threadIdx.x;   // 131072
    int hp = idx >> 10, d = idx & 1023;
    int h = hp >> 3, p = hp & 7;
    const float* qrow = g_q + (long)p*D_ + h*64;
    const float* wb   = W + ((long)D_ + h*64)*D_ + d;
    float acc = 0.f;
    #pragma unroll 8
    for (int j = 0; j < 64; j++) acc += qrow[j]*wb[(long)j*D_];
    g_qt[idx] = acc * 0.125f;
}

// ---------------- generic NT SGEMM: C[m,n] = sum_k A[m,k]*B[n,k] (+bias) ----------------
// z = batch*ksplit + kc. If batch==1 && B1: use B1/bias1 (dual-weight trick for stage G).
__launch_bounds__(256, 2)
__global__ void sgemm_nt(const float* __restrict__ A, int lda, long sA,
                         const float* __restrict__ B, int ldb, long sB,
                         const float* __restrict__ B1,
                         float* __restrict__ C, int ldc, long sC, long sCk,
                         const float* __restrict__ bias, const float* __restrict__ bias1,
                         int M, int N, int K, int ksplit) {
    __shared__ float As[8][128];
    __shared__ float Bs[8][128];
    int z = blockIdx.z;
    int batch = z / ksplit, kc = z - batch*ksplit;
    const float* Ab = A + (long)batch*sA;
    const float* Bb = B + (long)batch*sB;
    const float* bb = bias;
    if (batch == 1 && B1) { Bb = B1; bb = bias1; }
    float* Cb = C + (long)batch*sC + (long)kc*sCk;
    int Kc = K / ksplit, kbeg = kc*Kc, kend = kbeg + Kc;

    int tid = threadIdx.x;
    int tm = tid >> 4, tn = tid & 15;
    int m0 = blockIdx.y*128, n0 = blockIdx.x*128;
    int ar = tid >> 1, ac = (tid & 1)*4;

    float acc[8][8];
    #pragma unroll
    for (int i = 0; i < 8; i++)
        #pragma unroll
        for (int j = 0; j < 8; j++) acc[i][j] = 0.f;

    const float* Aptr = Ab + (long)(m0+ar)*lda;
    const float* Bptr = Bb + (long)(n0+ar)*ldb;
    bool am = (m0 + ar) < M, bn = (n0 + ar) < N;

    for (int k0 = kbeg; k0 < kend; k0 += 8) {
        float4 av = make_float4(0,0,0,0), bv = make_float4(0,0,0,0);
        if (am) av = *(const float4*)(Aptr + k0 + ac);
        if (bn) bv = *(const float4*)(Bptr + k0 + ac);
        __syncthreads();
        As[ac+0][ar] = av.x; As[ac+1][ar] = av.y; As[ac+2][ar] = av.z; As[ac+3][ar] = av.w;
        Bs[ac+0][ar] = bv.x; Bs[ac+1][ar] = bv.y; Bs[ac+2][ar] = bv.z; Bs[ac+3][ar] = bv.w;
        __syncthreads();
        #pragma unroll
        for (int k = 0; k < 8; k++) {
            float4 a0 = *(const float4*)&As[k][tm*8];
            float4 a1 = *(const float4*)&As[k][tm*8+4];
            float4 b0 = *(const float4*)&Bs[k][tn*8];
            float4 b1 = *(const float4*)&Bs[k][tn*8+4];
            float ra[8] = {a0.x,a0.y,a0.z,a0.w,a1.x,a1.y,a1.z,a1.w};
            float rb[8] = {b0.x,b0.y,b0.z,b0.w,b1.x,b1.y,b1.z,b1.w};
            #pragma unroll
            for (int i = 0; i < 8; i++)
                #pragma unroll
                for (int j = 0; j < 8; j++) acc[i][j] += ra[i]*rb[j];
        }
    }
    #pragma unroll
    for (int i = 0; i < 8; i++) {
        int m = m0 + tm*8 + i;
        if (m >= M) continue;
        #pragma unroll
        for (int j = 0; j < 8; j++) {
            int n = n0 + tn*8 + j;
            if (n >= N) continue;
            float v = acc[i][j];
            if (bb && ksplit == 1) v += bb[n];
            Cb[(long)m*ldc + n] = v;
        }
    }
}

// ---------------- generic NN SGEMM: C[m,n] = sum_k A[m,k]*B[k,n] (batched over z) ----------------
__launch_bounds__(256, 2)
__global__ void sgemm_nn(const float* __restrict__ A, int lda, long sA,
                         const float* __restrict__ B, int ldb, long sB,
                         float* __restrict__ C, int ldc, long sC,
                         int M, int N, int K) {
    __shared__ float As[8][128];
    __shared__ float Bs[8][128];
    int batch = blockIdx.z;
    const float* Ab = A + (long)batch*sA;
    const float* Bb = B + (long)batch*sB;
    float* Cb = C + (long)batch*sC;

    int tid = threadIdx.x;
    int tm = tid >> 4, tn = tid & 15;
    int m0 = blockIdx.y*128, n0 = blockIdx.x*128;
    int ar = tid >> 1, ac = (tid & 1)*4;   // A loader
    int br = tid >> 5, bc = (tid & 31)*4;  // B loader (8 k-rows x 128 n)

    float acc[8][8];
    #pragma unroll
    for (int i = 0; i < 8; i++)
        #pragma unroll
        for (int j = 0; j < 8; j++) acc[i][j] = 0.f;

    bool am = (m0 + ar) < M;
    bool bnOK = (n0 + bc) < N;

    for (int k0 = 0; k0 < K; k0 += 8) {
        float4 av = make_float4(0,0,0,0), bv = make_float4(0,0,0,0);
        if (am) av = *(const float4*)(Ab + (long)(m0+ar)*lda + k0 + ac);
        if (bnOK && (k0+br) < K) bv = *(const float4*)(Bb + (long)(k0+br)*ldb + n0 + bc);
        __syncthreads();
        As[ac+0][ar] = av.x; As[ac+1][ar] = av.y; As[ac+2][ar] = av.z; As[ac+3][ar] = av.w;
        *(float4*)&Bs[br][bc] = bv;
        __syncthreads();
        #pragma unroll
        for (int k = 0; k < 8; k++) {
            float4 a0 = *(const float4*)&As[k][tm*8];
            float4 a1 = *(const float4*)&As[k][tm*8+4];
            float4 b0 = *(const float4*)&Bs[k][tn*8];
            float4 b1 = *(const float4*)&Bs[k][tn*8+4];
            float ra[8] = {a0.x,a0.y,a0.z,a0.w,a1.x,a1.y,a1.z,a1.w};
            float rb[8] = {b0.x,b0.y,b0.z,b0.w,b1.x,b1.y,b1.z,b1.w};
            #pragma unroll
            for (int i = 0; i < 8; i++)
                #pragma unroll
                for (int j = 0; j < 8; j++) acc[i][j] += ra[i]*rb[j];
        }
    }
    #pragma unroll
    for (int i = 0; i < 8; i++) {
        int m = m0 + tm*8 + i;
        if (m >= M) continue;
        #pragma unroll
        for (int j = 0; j < 8; j++) {
            int n = n0 + tn*8 + j;
            if (n < N) Cb[(long)m*ldc + n] = acc[i][j];
        }
    }
}

// ---------------- masked softmax over s (attn written in place, 0 for s>=L) ----------------
__global__ void k_softmax() {
    int row = blockIdx.x;          // b*128 + hp
    int b = row >> 7;
    int L = g_len[b];
    float* r = g_scores + (long)row*S_;
    int t = threadIdx.x;
    float v[8];
    float mx = -1e30f;
    #pragma unroll
    for (int i = 0; i < 8; i++) {
        int s = t + i*256;
        v[i] = (s < L) ? r[s] : -1e30f;
        mx = fmaxf(mx, v[i]);
    }
    __shared__ float sh[256];
    sh[t] = mx; __syncthreads();
    for (int o = 128; o > 0; o >>= 1) { if (t < o) sh[t] = fmaxf(sh[t], sh[t+o]); __syncthreads(); }
    mx = sh[0]; __syncthreads();
    float sum = 0.f;
    #pragma unroll
    for (int i = 0; i < 8; i++) {
        int s = t + i*256;
        if (s < L) { v[i] = expf(v[i]-mx); sum += v[i]; } else v[i] = 0.f;
    }
    sh[t] = sum; __syncthreads();
    for (int o = 128; o > 0; o >>= 1) { if (t < o) sh[t] += sh[t+o]; __syncthreads(); }
    float tot = sh[0];
    float inv = (tot > 0.f) ? (1.f / tot) : 0.f;   // NaN guard: L==0 -> attn all zero
    #pragma unroll
    for (int i = 0; i < 8; i++) r[t + i*256] = v[i]*inv;
}

// ---------------- ctx[b,p,h*64+j] = Y[b,h*8+p,:] . Wv[h*64+j,:] + bv ----------------
__global__ void k_ctx(const float* __restrict__ W, const float* __restrict__ bias) {
    int h = blockIdx.x, b = blockIdx.y;
    __shared__ float As[8][33];
    __shared__ float Bs[64][33];
    int tid = threadIdx.x;
    int lr = tid >> 5, lc = tid & 31;
    const float* Yb = g_Y + ((long)b*128 + h*8)*D_;
    const float* Wb = W + (2L*D_ + h*64)*D_;
    float acc0 = 0.f, acc1 = 0.f;
    int p0 = tid >> 6, j0 = tid & 63;
    for (int k0 = 0; k0 < D_; k0 += 32) {
        __syncthreads();
        As[lr][lc] = Yb[(long)lr*D_ + k0 + lc];
        #pragma unroll
        for (int i = 0; i < 8; i++)
            Bs[i*8+lr][lc] = Wb[(long)(i*8+lr)*D_ + k0 + lc];
        __syncthreads();
        #pragma unroll
        for (int k = 0; k < 32; k++) {
            float bb = Bs[j0][k];
            acc0 += As[p0][k]*bb;
            acc1 += As[p0+4][k]*bb;
        }
    }
    float bj = bias[2L*D_ + h*64 + j0];
    g_ctx[((long)b*P_ + p0  )*D_ + h*64 + j0] = acc0 + bj;
    g_ctx[((long)b*P_ + p0+4)*D_ + h*64 + j0] = acc1 + bj;
}

// ---------------- pma rows: LN(queries + pooled(reduced) + out_b) -> summary[1..8] ----------------
__global__ void k_pma_ln(const float* __restrict__ queries, const float* __restrict__ outb,
                         const float* __restrict__ g, const float* __restrict__ bt) {
    int blk = blockIdx.x;  // 0..127
    int b = blk >> 3, p = blk & 7;
    int t = threadIdx.x;
    float x[4];
    float s1 = 0.f, s2 = 0.f;
    #pragma unroll
    for (int i = 0; i < 4; i++) {
        int d = t + i*256;
        float v = queries[(long)p*D_ + d] + outb[d];
        #pragma unroll
        for (int kc = 0; kc < KSPLIT_POOL; kc++)
            v += g_pooled[((long)kc*B_*P_ + (long)b*P_ + p)*D_ + d];
        x[i] = v; s1 += v; s2 += v*v;
    }
    __shared__ float sh1[256], sh2[256];
    sh1[t] = s1; sh2[t] = s2; __syncthreads();
    for (int o = 128; o > 0; o >>= 1) { if (t < o) { sh1[t]+=sh1[t+o]; sh2[t]+=sh2[t+o]; } __syncthreads(); }
    float mu = sh1[0]/D_;
    float var = sh2[0]/D_ - mu*mu;
    float rs = rsqrtf(var + 1e-5f);
    #pragma unroll
    for (int i = 0; i < 4; i++) {
        int d = t + i*256;
        g_summary[((long)b*NSUM + 1 + p)*D_ + d] = (x[i]-mu)*rs*g[d] + bt[d];
    }
}

// ---------------- cls + recent gather + mask flags ----------------
__global__ void k_summary(const float* __restrict__ X) {
    int t = blockIdx.x;   // 0..64
    int b = blockIdx.y;
    int L = g_len[b];
    int tid = threadIdx.x;
    if (t == 0) {
        const float* src = X + (long)b*S_*D_;
        float* dst = g_summary + (long)b*NSUM*D_;
        #pragma unroll
        for (int i = 0; i < 4; i++) { int d = tid + i*256; dst[d] = src[d]; }
        if (tid == 0) g_maskf[b*NSUM] = (L > 0) ? 1.f : 0.f;
        if (tid >= 1 && tid <= 8) g_maskf[b*NSUM + tid] = 1.f;  // pma always valid
    } else {
        int j = t - 1;
        int s = L - R_ + j;                       // original sequence index
        int valid = (s >= 1) && (L >= 1);          // token must come from X[:,1:]
        float* dst = g_summary + ((long)b*NSUM + 9 + j)*D_;
        if (valid) {
            const float* src = X + ((long)b*S_ + s)*D_;
            #pragma unroll
            for (int i = 0; i < 4; i++) { int d = tid + i*256; dst[d] = src[d]; }
        } else {
            #pragma unroll
            for (int i = 0; i < 4; i++) { int d = tid + i*256; dst[d] = 0.f; }
        }
        if (tid == 0) g_maskf[b*NSUM + 9 + j] = valid ? 1.f : 0.f;
    }
}

// ---------------- two LN variants of each summary row -> g_norm sections ----------------
__global__ void k_norm2(const float* __restrict__ gv, const float* __restrict__ bv,
                        const float* __restrict__ gg, const float* __restrict__ bg) {
    int r = blockIdx.x;   // 0..1167
    int t = threadIdx.x;
    const float* xr = g_summary + (long)r*D_;
    float x[4];
    float s1 = 0.f, s2 = 0.f;
    #pragma unroll
    for (int i = 0; i < 4; i++) {
        int d = t + i*256;
        float v = xr[d];
        x[i] = v; s1 += v; s2 += v*v;
    }
    __shared__ float sh1[256], sh2[256];
    sh1[t] = s1; sh2[t] = s2; __syncthreads();
    for (int o = 128; o > 0; o >>= 1) { if (t < o) { sh1[t]+=sh1[t+o]; sh2[t]+=sh2[t+o]; } __syncthreads(); }
    float mu = sh1[0]/D_;
    float var = sh2[0]/D_ - mu*mu;
    float rs = rsqrtf(fmaxf(var, 0.f) + 1e-5f);
    #pragma unroll
    for (int i = 0; i < 4; i++) {
        int d = t + i*256;
        float xn = (x[i]-mu)*rs;
        g_norm[(long)r*D_ + d]              = xn*gv[d] + bv[d];
        g_norm[(long)MPAD*D_ + (long)r*D_ + d] = xn*gg[d] + bg[d];
    }
}

// ---------------- epilogue: gated = sigmoid(gate)*silu(val)*mask ; write d_out ----------------
__global__ void k_out(float* __restrict__ out, long out_size) {
    long idx = (long)blockIdx.x*256 + threadIdx.x;
    if (idx >= out_size) return;
    const long NG = (long)NROWS*D_;
    if (idx < NG) {
        long r = idx >> 10;
        int d = (int)(idx & 1023);
        float vp = g_valgate[r*D_ + d];
        float gp = g_valgate[(long)MPAD*D_ + r*D_ + d];
        float sv = 1.f/(1.f + expf(-vp));
        float sg = 1.f/(1.f + expf(-gp));
        out[idx] = sg * (vp*sv) * g_maskf[r];
    } else {
        long mi = idx - NG;
        out[idx] = (mi < NROWS) ? g_maskf[mi] : 0.f;
    }
}

// =========================================================================================
extern "C" void kernel_launch(void* const* d_in, const int* in_sizes, int n_in,
                              void* d_out, int out_size) {
    const float*         X        = (const float*)d_in[0];
    const void*          vmask    = (const void*)d_in[1];
    const float*         queries  = (const float*)d_in[2];
    const float*         in_w     = (const float*)d_in[3];
    const float*         in_b     = (const float*)d_in[4];
    const float*         out_w    = (const float*)d_in[5];
    const float*         out_b    = (const float*)d_in[6];
    const float*         ln_pma_g = (const float*)d_in[7];
    const float*         ln_pma_b = (const float*)d_in[8];
    const float*         ln_v_g   = (const float*)d_in[9];
    const float*         ln_v_b   = (const float*)d_in[10];
    const float*         W_v      = (const float*)d_in[11];
    const float*         b_v      = (const float*)d_in[12];
    const float*         ln_g_g   = (const float*)d_in[13];
    const float*         ln_g_b   = (const float*)d_in[14];
    const float*         W_g      = (const float*)d_in[15];
    const float*         b_g      = (const float*)d_in[16];

    float *p_qt, *p_scores, *p_Y, *p_ctx, *p_pooled, *p_norm, *p_valgate;
    cudaGetSymbolAddress((void**)&p_qt,      g_qt);
    cudaGetSymbolAddress((void**)&p_scores,  g_scores);
    cudaGetSymbolAddress((void**)&p_Y,       g_Y);
    cudaGetSymbolAddress((void**)&p_ctx,     g_ctx);
    cudaGetSymbolAddress((void**)&p_pooled,  g_pooled);
    cudaGetSymbolAddress((void**)&p_norm,    g_norm);
    cudaGetSymbolAddress((void**)&p_valgate, g_valgate);

    // mask encoding detection + lengths
    k_mode<<<1, 1>>>((const int*)vmask);
    k_len<<<B_, 256>>>(vmask);
    // q = queries @ Wq^T + bq
    k_q<<<(P_*D_*32)/256, 256>>>(queries, in_w, in_b);
    // q~ (folds 1/sqrt(hd); bk dropped: softmax-invariant)
    k_qt<<<(128*D_)/256, 256>>>(in_w);
    // scores[b,hp,s] = q~[hp,:] . X[b,s,:]
    sgemm_nt<<<dim3(S_/128, 1, B_), 256>>>(
        p_qt, D_, 0L,
        X, D_, (long)S_*D_, nullptr,
        p_scores, S_, 128L*S_, 0L,
        nullptr, nullptr, 128, S_, D_, 1);
    // masked softmax (attn; 0 beyond L)
    k_softmax<<<B_*128, 256>>>();
    // Y[b,hp,:] = attn[b,hp,:] @ X[b]
    sgemm_nn<<<dim3(D_/128, 1, B_), 256>>>(
        p_scores, S_, 128L*S_,
        X, D_, (long)S_*D_,
        p_Y, D_, 128L*D_,
        128, D_, S_);
    // ctx = per-head Y @ Wv_h^T + bv
    k_ctx<<<dim3(H_, B_), 256>>>(in_w, in_b);
    // pooled = ctx @ out_w^T  (split-K partials, reduced in k_pma_ln; bias added there)
    sgemm_nt<<<dim3(D_/128, 1, KSPLIT_POOL), 256>>>(
        p_ctx, D_, 0L,
        out_w, D_, 0L, nullptr,
        p_pooled, D_, 0L, (long)B_*P_*D_,
        nullptr, nullptr, B_*P_, D_, D_, KSPLIT_POOL);
    // pma tokens = LN(queries + pooled + out_b)
    k_pma_ln<<<B_*P_, 256>>>(queries, out_b, ln_pma_g, ln_pma_b);
    // cls + recent gather + masks
    k_summary<<<dim3(1 + R_, B_), 256>>>(X);
    // LN_v and LN_g of all summary rows
    k_norm2<<<NROWS, 256>>>(ln_v_g, ln_v_b, ln_g_g, ln_g_b);
    // val = A_v @ W_v^T + b_v ; gate = A_g @ W_g^T + b_g  (one launch, z picks weights)
    sgemm_nt<<<dim3(D_/128, MPAD/128, 2), 256>>>(
        p_norm, D_, (long)MPAD*D_,
        W_v, D_, 0L, W_g,
        p_valgate, D_, (long)MPAD*D_, 0L,
        b_v, b_g, MPAD, D_, D_, 1);
    // epilogue + mask tail (covers every d_out element; poison-safe)
    long osz = (long)out_size;
    long nblk = (osz + 255) / 256;
    k_out<<<(unsigned)nblk, 256>>>((float*)d_out, osz);
}

// round 7
// speedup vs baseline: 2.4381x; 2.4381x over previous
#include <cuda_runtime.h>
#include <math.h>

// Problem constants (fixed by setup_inputs)
#define B_    16
#define S_    2048
#define D_    1024
#define H_    16
#define P_    8
#define R_    64
#define NSUM  73                  // 1 cls + 8 pma + 64 recent
#define NROWS (B_*NSUM)           // 1168
#define MPAD  1280                // padded row count for stage-G GEMM
#define KSPLIT_POOL 4

// ---------------- scratch (device globals; zero-initialized at load) ----------------
__device__ float g_q[P_*D_];
__device__ float g_qt[128*D_];
__device__ float g_scores[(long)B_*128*S_];          // also holds attn after softmax
__device__ float g_Y[(long)B_*128*D_];
__device__ float g_ctx[(long)B_*P_*D_];
__device__ float g_pooled[(long)KSPLIT_POOL*B_*P_*D_]; // split-K partials (no atomics)
__device__ float g_summary[(long)NROWS*D_];
__device__ float g_norm[2L*MPAD*D_];                 // [0]=LN_v rows, [1]=LN_g rows; pad rows stay 0
__device__ float g_valgate[2L*MPAD*D_];              // [0]=val pre-act, [1]=gate pre-act
__device__ float g_maskf[NROWS];
__device__ int   g_len[B_];
__device__ int   g_mode;                             // 1 = int32 mask, 0 = uint8 mask

// ---------------- tf32 helpers ----------------
__device__ __forceinline__ unsigned f2tf(float x) {
    unsigned u; asm("cvt.rna.tf32.f32 %0, %1;" : "=r"(u) : "f"(x)); return u;
}
__device__ __forceinline__ void mma_tf32(float c[4], const unsigned a[4], const unsigned b[2]) {
    asm volatile("mma.sync.aligned.m16n8k8.row.col.f32.tf32.tf32.f32 "
        "{%0,%1,%2,%3}, {%4,%5,%6,%7}, {%8,%9}, {%0,%1,%2,%3};"
        : "+f"(c[0]), "+f"(c[1]), "+f"(c[2]), "+f"(c[3])
        : "r"(a[0]), "r"(a[1]), "r"(a[2]), "r"(a[3]), "r"(b[0]), "r"(b[1]));
}

// ---------------- mask-encoding detection (reads first 16 bytes only; always safe) ----
__global__ void k_mode(const int* __restrict__ mask_as_int) {
    int w0 = mask_as_int[0], w1 = mask_as_int[1], w2 = mask_as_int[2], w3 = mask_as_int[3];
    int is_i32 = ((unsigned)w0 <= 1u) & ((unsigned)w1 <= 1u) &
                 ((unsigned)w2 <= 1u) & ((unsigned)w3 <= 1u);
    g_mode = is_i32;
}

// ---------------- lengths from valid_mask (dtype-adaptive) ----------------
__global__ void k_len(const void* __restrict__ mask) {
    int b = blockIdx.x, t = threadIdx.x;
    int mode = g_mode;
    int s = 0;
    if (mode) {
        const int* m = (const int*)mask;
        for (int i = t; i < S_; i += 256) s += (m[(long)b*S_ + i] != 0) ? 1 : 0;
    } else {
        const unsigned char* m = (const unsigned char*)mask;
        for (int i = t; i < S_; i += 256) s += m[(long)b*S_ + i] ? 1 : 0;
    }
    __shared__ int sh[256];
    sh[t] = s; __syncthreads();
    for (int o = 128; o > 0; o >>= 1) { if (t < o) sh[t] += sh[t+o]; __syncthreads(); }
    if (t == 0) g_len[b] = sh[0];
}

// ---------------- q = queries @ Wq^T + bq  (warp per output) ----------------
__global__ void k_q(const float* __restrict__ queries, const float* __restrict__ W,
                    const float* __restrict__ bias) {
    int w = (blockIdx.x*blockDim.x + threadIdx.x) >> 5;
    int lane = threadIdx.x & 31;
    if (w >= P_*D_) return;
    int p = w / D_, d = w % D_;
    const float* qr = queries + (long)p*D_;
    const float* wr = W + (long)d*D_;
    float acc = 0.f;
    for (int k = lane; k < D_; k += 32) acc += qr[k]*wr[k];
    for (int o = 16; o > 0; o >>= 1) acc += __shfl_down_sync(0xffffffffu, acc, o);
    if (lane == 0) g_q[(long)p*D_ + d] = acc + bias[d];
}

// ---------------- qt[hp,d] = (1/8) * sum_j q[p, h*64+j] * Wk[h*64+j, d] ----------------
__global__ void k_qt(const float* __restrict__ W) {
    int idx = blockIdx.x*blockDim.x + threadIdx.x;   // 131072
    int hp = idx >> 10, d = idx & 1023;
    int h = hp >> 3, p = hp & 7;
    const float* qrow = g_q + (long)p*D_ + h*64;
    const float* wb   = W + ((long)D_ + h*64)*D_ + d;
    float acc = 0.f;
    #pragma unroll 8
    for (int j = 0; j < 64; j++) acc += qrow[j]*wb[(long)j*D_];
    g_qt[idx] = acc * 0.125f;
}

// =========================================================================================
// tf32 tensor-core NT GEMM: C[m,n] = sum_k A[m,k]*B[n,k] (+bias). A row-major MxK,
// B row-major NxK. M,N multiples of 128; K multiple of 16. z: batch (strides sA/sB/sC);
// if z==1 && B1, swap to B1/bias1 (dual-weight trick for the val/gate stage).
// =========================================================================================
__launch_bounds__(256)
__global__ void tgemm_nt(const float* __restrict__ A, int lda, long sA,
                         const float* __restrict__ B, int ldb, long sB,
                         const float* __restrict__ B1,
                         float* __restrict__ C, int ldc, long sC,
                         const float* __restrict__ bias, const float* __restrict__ bias1,
                         int K) {
    __shared__ unsigned As[128][20];   // [row][k] stride 20: conflict-free fragment loads
    __shared__ unsigned Bs[128][20];
    int z = blockIdx.z;
    const float* Ab = A + (long)z*sA;
    const float* Bb = B + (long)z*sB;
    const float* bb = bias;
    if (z == 1 && B1) { Bb = B1; bb = bias1; }
    float* Cb = C + (long)z*sC;
    int m0 = blockIdx.y*128, n0 = blockIdx.x*128;
    int t = threadIdx.x;
    int lane = t & 31, wid = t >> 5;
    int m_off = (wid & 1)*64, n_off = (wid >> 1)*32;
    int lane4 = lane >> 2, lanem = lane & 3;

    float c[4][4][4];
    #pragma unroll
    for (int i = 0; i < 4; i++)
        #pragma unroll
        for (int j = 0; j < 4; j++)
            #pragma unroll
            for (int q = 0; q < 4; q++) c[i][j][q] = 0.f;

    int srow0 = t >> 2, srow1 = 64 + (t >> 2);
    int skg = (t & 3)*4;
    float4 apf[2], bpf[2];

    // prologue: load k-tile 0
    apf[0] = *(const float4*)(Ab + (long)(m0+srow0)*lda + skg);
    apf[1] = *(const float4*)(Ab + (long)(m0+srow1)*lda + skg);
    bpf[0] = *(const float4*)(Bb + (long)(n0+srow0)*ldb + skg);
    bpf[1] = *(const float4*)(Bb + (long)(n0+srow1)*ldb + skg);
    {
        uint4 ua0 = make_uint4(f2tf(apf[0].x), f2tf(apf[0].y), f2tf(apf[0].z), f2tf(apf[0].w));
        uint4 ua1 = make_uint4(f2tf(apf[1].x), f2tf(apf[1].y), f2tf(apf[1].z), f2tf(apf[1].w));
        uint4 ub0 = make_uint4(f2tf(bpf[0].x), f2tf(bpf[0].y), f2tf(bpf[0].z), f2tf(bpf[0].w));
        uint4 ub1 = make_uint4(f2tf(bpf[1].x), f2tf(bpf[1].y), f2tf(bpf[1].z), f2tf(bpf[1].w));
        *(uint4*)&As[srow0][skg] = ua0; *(uint4*)&As[srow1][skg] = ua1;
        *(uint4*)&Bs[srow0][skg] = ub0; *(uint4*)&Bs[srow1][skg] = ub1;
    }
    __syncthreads();

    int niter = K >> 4;
    for (int it = 0; it < niter; it++) {
        bool more = (it + 1 < niter);
        if (more) {
            int k0 = (it+1) << 4;
            apf[0] = *(const float4*)(Ab + (long)(m0+srow0)*lda + k0 + skg);
            apf[1] = *(const float4*)(Ab + (long)(m0+srow1)*lda + k0 + skg);
            bpf[0] = *(const float4*)(Bb + (long)(n0+srow0)*ldb + k0 + skg);
            bpf[1] = *(const float4*)(Bb + (long)(n0+srow1)*ldb + k0 + skg);
        }
        #pragma unroll
        for (int ks = 0; ks < 2; ks++) {
            int kk = ks*8 + lanem;
            unsigned a[4][4], b[4][2];
            #pragma unroll
            for (int i = 0; i < 4; i++) {
                int r = m_off + i*16 + lane4;
                a[i][0] = As[r][kk];   a[i][1] = As[r+8][kk];
                a[i][2] = As[r][kk+4]; a[i][3] = As[r+8][kk+4];
            }
            #pragma unroll
            for (int j = 0; j < 4; j++) {
                int r = n_off + j*8 + lane4;
                b[j][0] = Bs[r][kk];  b[j][1] = Bs[r][kk+4];
            }
            #pragma unroll
            for (int i = 0; i < 4; i++)
                #pragma unroll
                for (int j = 0; j < 4; j++) mma_tf32(c[i][j], a[i], b[j]);
        }
        __syncthreads();
        if (more) {
            uint4 ua0 = make_uint4(f2tf(apf[0].x), f2tf(apf[0].y), f2tf(apf[0].z), f2tf(apf[0].w));
            uint4 ua1 = make_uint4(f2tf(apf[1].x), f2tf(apf[1].y), f2tf(apf[1].z), f2tf(apf[1].w));
            uint4 ub0 = make_uint4(f2tf(bpf[0].x), f2tf(bpf[0].y), f2tf(bpf[0].z), f2tf(bpf[0].w));
            uint4 ub1 = make_uint4(f2tf(bpf[1].x), f2tf(bpf[1].y), f2tf(bpf[1].z), f2tf(bpf[1].w));
            *(uint4*)&As[srow0][skg] = ua0; *(uint4*)&As[srow1][skg] = ua1;
            *(uint4*)&Bs[srow0][skg] = ub0; *(uint4*)&Bs[srow1][skg] = ub1;
        }
        __syncthreads();
    }

    #pragma unroll
    for (int i = 0; i < 4; i++) {
        int row = m0 + m_off + i*16 + lane4;
        #pragma unroll
        for (int j = 0; j < 4; j++) {
            int col = n0 + n_off + j*8 + lanem*2;
            float bv0 = bb ? bb[col] : 0.f;
            float bv1 = bb ? bb[col+1] : 0.f;
            float2 lo = make_float2(c[i][j][0] + bv0, c[i][j][1] + bv1);
            float2 hi = make_float2(c[i][j][2] + bv0, c[i][j][3] + bv1);
            *(float2*)(Cb + (long)row*ldc + col)     = lo;
            *(float2*)(Cb + (long)(row+8)*ldc + col) = hi;
        }
    }
}

// =========================================================================================
// tf32 tensor-core NN GEMM: C[m,n] = sum_k A[m,k]*B[k,n]. A row-major MxK, B row-major KxN.
// M,N multiples of 128; K multiple of 16. Batched over z.
// =========================================================================================
__launch_bounds__(256)
__global__ void tgemm_nn(const float* __restrict__ A, int lda, long sA,
                         const float* __restrict__ B, int ldb, long sB,
                         float* __restrict__ C, int ldc, long sC,
                         int K) {
    __shared__ unsigned As[128][20];
    __shared__ unsigned Bs[16][136];   // [k][n] stride 136: conflict-free b-frag loads
    int z = blockIdx.z;
    const float* Ab = A + (long)z*sA;
    const float* Bb = B + (long)z*sB;
    float* Cb = C + (long)z*sC;
    int m0 = blockIdx.y*128, n0 = blockIdx.x*128;
    int t = threadIdx.x;
    int lane = t & 31, wid = t >> 5;
    int m_off = (wid & 1)*64, n_off = (wid >> 1)*32;
    int lane4 = lane >> 2, lanem = lane & 3;

    float c[4][4][4];
    #pragma unroll
    for (int i = 0; i < 4; i++)
        #pragma unroll
        for (int j = 0; j < 4; j++)
            #pragma unroll
            for (int q = 0; q < 4; q++) c[i][j][q] = 0.f;

    int arow0 = t >> 2, arow1 = 64 + (t >> 2);
    int akg = (t & 3)*4;
    int bk0 = t >> 5, bk1 = 8 + (t >> 5);      // idx&31 same both reps
    int bn = (t & 31)*4;
    float4 apf[2], bpf[2];

    apf[0] = *(const float4*)(Ab + (long)(m0+arow0)*lda + akg);
    apf[1] = *(const float4*)(Ab + (long)(m0+arow1)*lda + akg);
    bpf[0] = *(const float4*)(Bb + (long)bk0*ldb + n0 + bn);
    bpf[1] = *(const float4*)(Bb + (long)bk1*ldb + n0 + bn);
    {
        uint4 ua0 = make_uint4(f2tf(apf[0].x), f2tf(apf[0].y), f2tf(apf[0].z), f2tf(apf[0].w));
        uint4 ua1 = make_uint4(f2tf(apf[1].x), f2tf(apf[1].y), f2tf(apf[1].z), f2tf(apf[1].w));
        uint4 ub0 = make_uint4(f2tf(bpf[0].x), f2tf(bpf[0].y), f2tf(bpf[0].z), f2tf(bpf[0].w));
        uint4 ub1 = make_uint4(f2tf(bpf[1].x), f2tf(bpf[1].y), f2tf(bpf[1].z), f2tf(bpf[1].w));
        *(uint4*)&As[arow0][akg] = ua0; *(uint4*)&As[arow1][akg] = ua1;
        *(uint4*)&Bs[bk0][bn] = ub0;    *(uint4*)&Bs[bk1][bn] = ub1;
    }
    __syncthreads();

    int niter = K >> 4;
    for (int it = 0; it < niter; it++) {
        bool more = (it + 1 < niter);
        if (more) {
            int k0 = (it+1) << 4;
            apf[0] = *(const float4*)(Ab + (long)(m0+arow0)*lda + k0 + akg);
            apf[1] = *(const float4*)(Ab + (long)(m0+arow1)*lda + k0 + akg);
            bpf[0] = *(const float4*)(Bb + (long)(k0+bk0)*ldb + n0 + bn);
            bpf[1] = *(const float4*)(Bb + (long)(k0+bk1)*ldb + n0 + bn);
        }
        #pragma unroll
        for (int ks = 0; ks < 2; ks++) {
            int kk = ks*8 + lanem;
            unsigned a[4][4], b[4][2];
            #pragma unroll
            for (int i = 0; i < 4; i++) {
                int r = m_off + i*16 + lane4;
                a[i][0] = As[r][kk];   a[i][1] = As[r+8][kk];
                a[i][2] = As[r][kk+4]; a[i][3] = As[r+8][kk+4];
            }
            #pragma unroll
            for (int j = 0; j < 4; j++) {
                int col = n_off + j*8 + lane4;
                b[j][0] = Bs[kk][col];  b[j][1] = Bs[kk+4][col];
            }
            #pragma unroll
            for (int i = 0; i < 4; i++)
                #pragma unroll
                for (int j = 0; j < 4; j++) mma_tf32(c[i][j], a[i], b[j]);
        }
        __syncthreads();
        if (more) {
            uint4 ua0 = make_uint4(f2tf(apf[0].x), f2tf(apf[0].y), f2tf(apf[0].z), f2tf(apf[0].w));
            uint4 ua1 = make_uint4(f2tf(apf[1].x), f2tf(apf[1].y), f2tf(apf[1].z), f2tf(apf[1].w));
            uint4 ub0 = make_uint4(f2tf(bpf[0].x), f2tf(bpf[0].y), f2tf(bpf[0].z), f2tf(bpf[0].w));
            uint4 ub1 = make_uint4(f2tf(bpf[1].x), f2tf(bpf[1].y), f2tf(bpf[1].z), f2tf(bpf[1].w));
            *(uint4*)&As[arow0][akg] = ua0; *(uint4*)&As[arow1][akg] = ua1;
            *(uint4*)&Bs[bk0][bn] = ub0;    *(uint4*)&Bs[bk1][bn] = ub1;
        }
        __syncthreads();
    }

    #pragma unroll
    for (int i = 0; i < 4; i++) {
        int row = m0 + m_off + i*16 + lane4;
        #pragma unroll
        for (int j = 0; j < 4; j++) {
            int col = n0 + n_off + j*8 + lanem*2;
            float2 lo = make_float2(c[i][j][0], c[i][j][1]);
            float2 hi = make_float2(c[i][j][2], c[i][j][3]);
            *(float2*)(Cb + (long)row*ldc + col)     = lo;
            *(float2*)(Cb + (long)(row+8)*ldc + col) = hi;
        }
    }
}

// ---------------- fp32 NT SGEMM (kept for small pooled stage, split-K) ----------------
__launch_bounds__(256, 2)
__global__ void sgemm_nt(const float* __restrict__ A, int lda,
                         const float* __restrict__ B, int ldb,
                         float* __restrict__ C, int ldc, long sCk,
                         int M, int N, int K, int ksplit) {
    __shared__ float As[8][128];
    __shared__ float Bs[8][128];
    int kc = blockIdx.z;
    float* Cb = C + (long)kc*sCk;
    int Kc = K / ksplit, kbeg = kc*Kc, kend = kbeg + Kc;

    int tid = threadIdx.x;
    int tm = tid >> 4, tn = tid & 15;
    int m0 = blockIdx.y*128, n0 = blockIdx.x*128;
    int ar = tid >> 1, ac = (tid & 1)*4;

    float acc[8][8];
    #pragma unroll
    for (int i = 0; i < 8; i++)
        #pragma unroll
        for (int j = 0; j < 8; j++) acc[i][j] = 0.f;

    const float* Aptr = A + (long)(m0+ar)*lda;
    const float* Bptr = B + (long)(n0+ar)*ldb;
    bool am = (m0 + ar) < M, bn = (n0 + ar) < N;

    for (int k0 = kbeg; k0 < kend; k0 += 8) {
        float4 av = make_float4(0,0,0,0), bv = make_float4(0,0,0,0);
        if (am) av = *(const float4*)(Aptr + k0 + ac);
        if (bn) bv = *(const float4*)(Bptr + k0 + ac);
        __syncthreads();
        As[ac+0][ar] = av.x; As[ac+1][ar] = av.y; As[ac+2][ar] = av.z; As[ac+3][ar] = av.w;
        Bs[ac+0][ar] = bv.x; Bs[ac+1][ar] = bv.y; Bs[ac+2][ar] = bv.z; Bs[ac+3][ar] = bv.w;
        __syncthreads();
        #pragma unroll
        for (int k = 0; k < 8; k++) {
            float4 a0 = *(const float4*)&As[k][tm*8];
            float4 a1 = *(const float4*)&As[k][tm*8+4];
            float4 b0 = *(const float4*)&Bs[k][tn*8];
            float4 b1 = *(const float4*)&Bs[k][tn*8+4];
            float ra[8] = {a0.x,a0.y,a0.z,a0.w,a1.x,a1.y,a1.z,a1.w};
            float rb[8] = {b0.x,b0.y,b0.z,b0.w,b1.x,b1.y,b1.z,b1.w};
            #pragma unroll
            for (int i = 0; i < 8; i++)
                #pragma unroll
                for (int j = 0; j < 8; j++) acc[i][j] += ra[i]*rb[j];
        }
    }
    #pragma unroll
    for (int i = 0; i < 8; i++) {
        int m = m0 + tm*8 + i;
        if (m >= M) continue;
        #pragma unroll
        for (int j = 0; j < 8; j++) {
            int n = n0 + tn*8 + j;
            if (n < N) Cb[(long)m*ldc + n] = acc[i][j];
        }
    }
}

// ---------------- masked softmax over s (attn written in place, 0 for s>=L) ----------------
__global__ void k_softmax() {
    int row = blockIdx.x;          // b*128 + hp
    int b = row >> 7;
    int L = g_len[b];
    float* r = g_scores + (long)row*S_;
    int t = threadIdx.x;
    float v[8];
    float mx = -1e30f;
    #pragma unroll
    for (int i = 0; i < 8; i++) {
        int s = t + i*256;
        v[i] = (s < L) ? r[s] : -1e30f;
        mx = fmaxf(mx, v[i]);
    }
    __shared__ float sh[256];
    sh[t] = mx; __syncthreads();
    for (int o = 128; o > 0; o >>= 1) { if (t < o) sh[t] = fmaxf(sh[t], sh[t+o]); __syncthreads(); }
    mx = sh[0]; __syncthreads();
    float sum = 0.f;
    #pragma unroll
    for (int i = 0; i < 8; i++) {
        int s = t + i*256;
        if (s < L) { v[i] = expf(v[i]-mx); sum += v[i]; } else v[i] = 0.f;
    }
    sh[t] = sum; __syncthreads();
    for (int o = 128; o > 0; o >>= 1) { if (t < o) sh[t] += sh[t+o]; __syncthreads(); }
    float tot = sh[0];
    float inv = (tot > 0.f) ? (1.f / tot) : 0.f;   // NaN guard
    #pragma unroll
    for (int i = 0; i < 8; i++) r[t + i*256] = v[i]*inv;
}

// ---------------- ctx[b,p,h*64+j] = Y[b,h*8+p,:] . Wv[h*64+j,:] + bv ----------------
__global__ void k_ctx(const float* __restrict__ W, const float* __restrict__ bias) {
    int h = blockIdx.x, b = blockIdx.y;
    __shared__ float As[8][33];
    __shared__ float Bs[64][33];
    int tid = threadIdx.x;
    int lr = tid >> 5, lc = tid & 31;
    const float* Yb = g_Y + ((long)b*128 + h*8)*D_;
    const float* Wb = W + (2L*D_ + h*64)*D_;
    float acc0 = 0.f, acc1 = 0.f;
    int p0 = tid >> 6, j0 = tid & 63;
    for (int k0 = 0; k0 < D_; k0 += 32) {
        __syncthreads();
        As[lr][lc] = Yb[(long)lr*D_ + k0 + lc];
        #pragma unroll
        for (int i = 0; i < 8; i++)
            Bs[i*8+lr][lc] = Wb[(long)(i*8+lr)*D_ + k0 + lc];
        __syncthreads();
        #pragma unroll
        for (int k = 0; k < 32; k++) {
            float bb = Bs[j0][k];
            acc0 += As[p0][k]*bb;
            acc1 += As[p0+4][k]*bb;
        }
    }
    float bj = bias[2L*D_ + h*64 + j0];
    g_ctx[((long)b*P_ + p0  )*D_ + h*64 + j0] = acc0 + bj;
    g_ctx[((long)b*P_ + p0+4)*D_ + h*64 + j0] = acc1 + bj;
}

// ---------------- pma rows: LN(queries + pooled(reduced) + out_b) -> summary[1..8] ----------------
__global__ void k_pma_ln(const float* __restrict__ queries, const float* __restrict__ outb,
                         const float* __restrict__ g, const float* __restrict__ bt) {
    int blk = blockIdx.x;  // 0..127
    int b = blk >> 3, p = blk & 7;
    int t = threadIdx.x;
    float x[4];
    float s1 = 0.f, s2 = 0.f;
    #pragma unroll
    for (int i = 0; i < 4; i++) {
        int d = t + i*256;
        float v = queries[(long)p*D_ + d] + outb[d];
        #pragma unroll
        for (int kc = 0; kc < KSPLIT_POOL; kc++)
            v += g_pooled[((long)kc*B_*P_ + (long)b*P_ + p)*D_ + d];
        x[i] = v; s1 += v; s2 += v*v;
    }
    __shared__ float sh1[256], sh2[256];
    sh1[t] = s1; sh2[t] = s2; __syncthreads();
    for (int o = 128; o > 0; o >>= 1) { if (t < o) { sh1[t]+=sh1[t+o]; sh2[t]+=sh2[t+o]; } __syncthreads(); }
    float mu = sh1[0]/D_;
    float var = sh2[0]/D_ - mu*mu;
    float rs = rsqrtf(var + 1e-5f);
    #pragma unroll
    for (int i = 0; i < 4; i++) {
        int d = t + i*256;
        g_summary[((long)b*NSUM + 1 + p)*D_ + d] = (x[i]-mu)*rs*g[d] + bt[d];
    }
}

// ---------------- cls + recent gather + mask flags ----------------
__global__ void k_summary(const float* __restrict__ X) {
    int t = blockIdx.x;   // 0..64
    int b = blockIdx.y;
    int L = g_len[b];
    int tid = threadIdx.x;
    if (t == 0) {
        const float* src = X + (long)b*S_*D_;
        float* dst = g_summary + (long)b*NSUM*D_;
        #pragma unroll
        for (int i = 0; i < 4; i++) { int d = tid + i*256; dst[d] = src[d]; }
        if (tid == 0) g_maskf[b*NSUM] = (L > 0) ? 1.f : 0.f;
        if (tid >= 1 && tid <= 8) g_maskf[b*NSUM + tid] = 1.f;  // pma always valid
    } else {
        int j = t - 1;
        int s = L - R_ + j;                        // original sequence index
        int valid = (s >= 1) && (L >= 1);          // token must come from X[:,1:]
        float* dst = g_summary + ((long)b*NSUM + 9 + j)*D_;
        if (valid) {
            const float* src = X + ((long)b*S_ + s)*D_;
            #pragma unroll
            for (int i = 0; i < 4; i++) { int d = tid + i*256; dst[d] = src[d]; }
        } else {
            #pragma unroll
            for (int i = 0; i < 4; i++) { int d = tid + i*256; dst[d] = 0.f; }
        }
        if (tid == 0) g_maskf[b*NSUM + 9 + j] = valid ? 1.f : 0.f;
    }
}

// ---------------- two LN variants of each summary row -> g_norm sections ----------------
__global__ void k_norm2(const float* __restrict__ gv, const float* __restrict__ bv,
                        const float* __restrict__ gg, const float* __restrict__ bg) {
    int r = blockIdx.x;   // 0..1167
    int t = threadIdx.x;
    const float* xr = g_summary + (long)r*D_;
    float x[4];
    float s1 = 0.f, s2 = 0.f;
    #pragma unroll
    for (int i = 0; i < 4; i++) {
        int d = t + i*256;
        float v = xr[d];
        x[i] = v; s1 += v; s2 += v*v;
    }
    __shared__ float sh1[256], sh2[256];
    sh1[t] = s1; sh2[t] = s2; __syncthreads();
    for (int o = 128; o > 0; o >>= 1) { if (t < o) { sh1[t]+=sh1[t+o]; sh2[t]+=sh2[t+o]; } __syncthreads(); }
    float mu = sh1[0]/D_;
    float var = sh2[0]/D_ - mu*mu;
    float rs = rsqrtf(fmaxf(var, 0.f) + 1e-5f);
    #pragma unroll
    for (int i = 0; i < 4; i++) {
        int d = t + i*256;
        float xn = (x[i]-mu)*rs;
        g_norm[(long)r*D_ + d]                 = xn*gv[d] + bv[d];
        g_norm[(long)MPAD*D_ + (long)r*D_ + d] = xn*gg[d] + bg[d];
    }
}

// ---------------- epilogue: gated = sigmoid(gate)*silu(val)*mask ; write d_out ----------------
__global__ void k_out(float* __restrict__ out, long out_size) {
    long idx = (long)blockIdx.x*256 + threadIdx.x;
    if (idx >= out_size) return;
    const long NG = (long)NROWS*D_;
    if (idx < NG) {
        long r = idx >> 10;
        int d = (int)(idx & 1023);
        float vp = g_valgate[r*D_ + d];
        float gp = g_valgate[(long)MPAD*D_ + r*D_ + d];
        float sv = 1.f/(1.f + expf(-vp));
        float sg = 1.f/(1.f + expf(-gp));
        out[idx] = sg * (vp*sv) * g_maskf[r];
    } else {
        long mi = idx - NG;
        out[idx] = (mi < NROWS) ? g_maskf[mi] : 0.f;
    }
}

// =========================================================================================
extern "C" void kernel_launch(void* const* d_in, const int* in_sizes, int n_in,
                              void* d_out, int out_size) {
    const float*         X        = (const float*)d_in[0];
    const void*          vmask    = (const void*)d_in[1];
    const float*         queries  = (const float*)d_in[2];
    const float*         in_w     = (const float*)d_in[3];
    const float*         in_b     = (const float*)d_in[4];
    const float*         out_w    = (const float*)d_in[5];
    const float*         out_b    = (const float*)d_in[6];
    const float*         ln_pma_g = (const float*)d_in[7];
    const float*         ln_pma_b = (const float*)d_in[8];
    const float*         ln_v_g   = (const float*)d_in[9];
    const float*         ln_v_b   = (const float*)d_in[10];
    const float*         W_v      = (const float*)d_in[11];
    const float*         b_v      = (const float*)d_in[12];
    const float*         ln_g_g   = (const float*)d_in[13];
    const float*         ln_g_b   = (const float*)d_in[14];
    const float*         W_g      = (const float*)d_in[15];
    const float*         b_g      = (const float*)d_in[16];

    float *p_qt, *p_scores, *p_Y, *p_ctx, *p_pooled, *p_norm, *p_valgate;
    cudaGetSymbolAddress((void**)&p_qt,      g_qt);
    cudaGetSymbolAddress((void**)&p_scores,  g_scores);
    cudaGetSymbolAddress((void**)&p_Y,       g_Y);
    cudaGetSymbolAddress((void**)&p_ctx,     g_ctx);
    cudaGetSymbolAddress((void**)&p_pooled,  g_pooled);
    cudaGetSymbolAddress((void**)&p_norm,    g_norm);
    cudaGetSymbolAddress((void**)&p_valgate, g_valgate);

    // mask encoding detection + lengths
    k_mode<<<1, 1>>>((const int*)vmask);
    k_len<<<B_, 256>>>(vmask);
    // q = queries @ Wq^T + bq
    k_q<<<(P_*D_*32)/256, 256>>>(queries, in_w, in_b);
    // q~ (folds 1/sqrt(hd); bk dropped: softmax-invariant)
    k_qt<<<(128*D_)/256, 256>>>(in_w);
    // scores[b,hp,s] = q~[hp,:] . X[b,s,:]   — tf32 tensor cores
    tgemm_nt<<<dim3(S_/128, 1, B_), 256>>>(
        p_qt, D_, 0L,
        X, D_, (long)S_*D_, nullptr,
        p_scores, S_, 128L*S_,
        nullptr, nullptr, D_);
    // masked softmax (attn; 0 beyond L)
    k_softmax<<<B_*128, 256>>>();
    // Y[b,hp,:] = attn[b,hp,:] @ X[b]       — tf32 tensor cores
    tgemm_nn<<<dim3(D_/128, 1, B_), 256>>>(
        p_scores, S_, 128L*S_,
        X, D_, (long)S_*D_,
        p_Y, D_, 128L*D_,
        S_);
    // ctx = per-head Y @ Wv_h^T + bv
    k_ctx<<<dim3(H_, B_), 256>>>(in_w, in_b);
    // pooled = ctx @ out_w^T  (split-K fp32 partials, reduced in k_pma_ln)
    sgemm_nt<<<dim3(D_/128, 1, KSPLIT_POOL), 256>>>(
        p_ctx, D_, out_w, D_,
        p_pooled, D_, (long)B_*P_*D_,
        B_*P_, D_, D_, KSPLIT_POOL);
    // pma tokens = LN(queries + pooled + out_b)
    k_pma_ln<<<B_*P_, 256>>>(queries, out_b, ln_pma_g, ln_pma_b);
    // cls + recent gather + masks
    k_summary<<<dim3(1 + R_, B_), 256>>>(X);
    // LN_v and LN_g of all summary rows
    k_norm2<<<NROWS, 256>>>(ln_v_g, ln_v_b, ln_g_g, ln_g_b);
    // val/gate dual GEMM — tf32 tensor cores (z=0: W_v,b_v; z=1: W_g,b_g)
    tgemm_nt<<<dim3(D_/128, MPAD/128, 2), 256>>>(
        p_norm, D_, (long)MPAD*D_,
        W_v, D_, 0L, W_g,
        p_valgate, D_, (long)MPAD*D_,
        b_v, b_g, D_);
    // epilogue + mask tail (covers every d_out element; poison-safe)
    long osz = (long)out_size;
    long nblk = (osz + 255) / 256;
    k_out<<<(unsigned)nblk, 256>>>((float*)d_out, osz);
}

// round 8
// speedup vs baseline: 2.5317x; 1.0384x over previous
#include <cuda_runtime.h>
#include <math.h>

// Problem constants (fixed by setup_inputs)
#define B_    16
#define S_    2048
#define D_    1024
#define H_    16
#define P_    8
#define R_    64
#define NSUM  73                  // 1 cls + 8 pma + 64 recent
#define NROWS (B_*NSUM)           // 1168
#define MPAD  1280                // padded row count for stage-G GEMM
#define KSPLIT_POOL 4

// ---------------- scratch (device globals; zero-initialized at load) ----------------
__device__ float g_q[P_*D_];
__device__ float g_qt[128*D_];
__device__ float g_scores[(long)B_*128*S_];          // also holds attn after softmax
__device__ float g_Y[(long)B_*128*D_];
__device__ float g_ctx[(long)B_*P_*D_];
__device__ float g_pooled[(long)KSPLIT_POOL*B_*P_*D_]; // split-K partials (no atomics)
__device__ float g_summary[(long)NROWS*D_];
__device__ float g_norm[2L*MPAD*D_];                 // [0]=LN_v rows, [1]=LN_g rows; pad rows stay 0
__device__ float g_valgate[2L*MPAD*D_];              // [0]=val pre-act, [1]=gate pre-act
__device__ float g_maskf[NROWS];
__device__ int   g_len[B_];

// ---------------- tf32 helpers ----------------
__device__ __forceinline__ unsigned f2tf(float x) {
    unsigned u; asm("cvt.rna.tf32.f32 %0, %1;" : "=r"(u) : "f"(x)); return u;
}
__device__ __forceinline__ void mma_tf32(float c[4], const unsigned a[4], const unsigned b[2]) {
    asm volatile("mma.sync.aligned.m16n8k8.row.col.f32.tf32.tf32.f32 "
        "{%0,%1,%2,%3}, {%4,%5,%6,%7}, {%8,%9}, {%0,%1,%2,%3};"
        : "+f"(c[0]), "+f"(c[1]), "+f"(c[2]), "+f"(c[3])
        : "r"(a[0]), "r"(a[1]), "r"(a[2]), "r"(a[3]), "r"(b[0]), "r"(b[1]));
}

// ---------------- lengths from valid_mask (dtype-adaptive; mode detected in-block) ----
__global__ void k_len(const void* __restrict__ mask) {
    int b = blockIdx.x, t = threadIdx.x;
    // bool->int32: first 4 words are 0/1. bool->uint8: words pack 4 bool bytes.
    const int* mi = (const int*)mask;
    int w0 = mi[0], w1 = mi[1], w2 = mi[2], w3 = mi[3];
    int mode = ((unsigned)w0 <= 1u) & ((unsigned)w1 <= 1u) &
               ((unsigned)w2 <= 1u) & ((unsigned)w3 <= 1u);
    int s = 0;
    if (mode) {
        const int* m = (const int*)mask;
        for (int i = t; i < S_; i += 256) s += (m[(long)b*S_ + i] != 0) ? 1 : 0;
    } else {
        const unsigned char* m = (const unsigned char*)mask;
        for (int i = t; i < S_; i += 256) s += m[(long)b*S_ + i] ? 1 : 0;
    }
    __shared__ int sh[256];
    sh[t] = s; __syncthreads();
    for (int o = 128; o > 0; o >>= 1) { if (t < o) sh[t] += sh[t+o]; __syncthreads(); }
    if (t == 0) g_len[b] = sh[0];
}

// ---------------- q = queries @ Wq^T + bq  (warp per output) ----------------
__global__ void k_q(const float* __restrict__ queries, const float* __restrict__ W,
                    const float* __restrict__ bias) {
    int w = (blockIdx.x*blockDim.x + threadIdx.x) >> 5;
    int lane = threadIdx.x & 31;
    if (w >= P_*D_) return;
    int p = w / D_, d = w % D_;
    const float* qr = queries + (long)p*D_;
    const float* wr = W + (long)d*D_;
    float acc = 0.f;
    for (int k = lane; k < D_; k += 32) acc += qr[k]*wr[k];
    for (int o = 16; o > 0; o >>= 1) acc += __shfl_down_sync(0xffffffffu, acc, o);
    if (lane == 0) g_q[(long)p*D_ + d] = acc + bias[d];
}

// ---------------- qt[hp,d] = (1/8) * sum_j q[p, h*64+j] * Wk[h*64+j, d] ----------------
__global__ void k_qt(const float* __restrict__ W) {
    int idx = blockIdx.x*blockDim.x + threadIdx.x;   // 131072
    int hp = idx >> 10, d = idx & 1023;
    int h = hp >> 3, p = hp & 7;
    const float* qrow = g_q + (long)p*D_ + h*64;
    const float* wb   = W + ((long)D_ + h*64)*D_ + d;
    float acc = 0.f;
    #pragma unroll 8
    for (int j = 0; j < 64; j++) acc += qrow[j]*wb[(long)j*D_];
    g_qt[idx] = acc * 0.125f;
}

// =========================================================================================
// tf32 tensor-core NT GEMM: C[m,n] = sum_k A[m,k]*B[n,k] (+bias). A row-major MxK,
// B row-major NxK. M,N multiples of 128; K multiple of 16. z: batch (strides sA/sB/sC);
// if z==1 && B1, swap to B1/bias1 (dual-weight trick for the val/gate stage).
// If lens != nullptr: skip the whole block when n0 >= lens[z] (masked-out score columns;
// softmax never reads them).
// =========================================================================================
__launch_bounds__(256)
__global__ void tgemm_nt(const float* __restrict__ A, int lda, long sA,
                         const float* __restrict__ B, int ldb, long sB,
                         const float* __restrict__ B1,
                         float* __restrict__ C, int ldc, long sC,
                         const float* __restrict__ bias, const float* __restrict__ bias1,
                         int K, const int* __restrict__ lens) {
    __shared__ unsigned As[128][20];   // [row][k] stride 20: conflict-free fragment loads
    __shared__ unsigned Bs[128][20];
    int z = blockIdx.z;
    int m0 = blockIdx.y*128, n0 = blockIdx.x*128;
    if (lens && n0 >= lens[z]) return;           // dead score columns: exact skip
    const float* Ab = A + (long)z*sA;
    const float* Bb = B + (long)z*sB;
    const float* bb = bias;
    if (z == 1 && B1) { Bb = B1; bb = bias1; }
    float* Cb = C + (long)z*sC;
    int t = threadIdx.x;
    int lane = t & 31, wid = t >> 5;
    int m_off = (wid & 1)*64, n_off = (wid >> 1)*32;
    int lane4 = lane >> 2, lanem = lane & 3;

    float c[4][4][4];
    #pragma unroll
    for (int i = 0; i < 4; i++)
        #pragma unroll
        for (int j = 0; j < 4; j++)
            #pragma unroll
            for (int q = 0; q < 4; q++) c[i][j][q] = 0.f;

    int srow0 = t >> 2, srow1 = 64 + (t >> 2);
    int skg = (t & 3)*4;
    float4 apf[2], bpf[2];

    // prologue: load k-tile 0
    apf[0] = *(const float4*)(Ab + (long)(m0+srow0)*lda + skg);
    apf[1] = *(const float4*)(Ab + (long)(m0+srow1)*lda + skg);
    bpf[0] = *(const float4*)(Bb + (long)(n0+srow0)*ldb + skg);
    bpf[1] = *(const float4*)(Bb + (long)(n0+srow1)*ldb + skg);
    {
        uint4 ua0 = make_uint4(f2tf(apf[0].x), f2tf(apf[0].y), f2tf(apf[0].z), f2tf(apf[0].w));
        uint4 ua1 = make_uint4(f2tf(apf[1].x), f2tf(apf[1].y), f2tf(apf[1].z), f2tf(apf[1].w));
        uint4 ub0 = make_uint4(f2tf(bpf[0].x), f2tf(bpf[0].y), f2tf(bpf[0].z), f2tf(bpf[0].w));
        uint4 ub1 = make_uint4(f2tf(bpf[1].x), f2tf(bpf[1].y), f2tf(bpf[1].z), f2tf(bpf[1].w));
        *(uint4*)&As[srow0][skg] = ua0; *(uint4*)&As[srow1][skg] = ua1;
        *(uint4*)&Bs[srow0][skg] = ub0; *(uint4*)&Bs[srow1][skg] = ub1;
    }
    __syncthreads();

    int niter = K >> 4;
    for (int it = 0; it < niter; it++) {
        bool more = (it + 1 < niter);
        if (more) {
            int k0 = (it+1) << 4;
            apf[0] = *(const float4*)(Ab + (long)(m0+srow0)*lda + k0 + skg);
            apf[1] = *(const float4*)(Ab + (long)(m0+srow1)*lda + k0 + skg);
            bpf[0] = *(const float4*)(Bb + (long)(n0+srow0)*ldb + k0 + skg);
            bpf[1] = *(const float4*)(Bb + (long)(n0+srow1)*ldb + k0 + skg);
        }
        #pragma unroll
        for (int ks = 0; ks < 2; ks++) {
            int kk = ks*8 + lanem;
            unsigned a[4][4], b[4][2];
            #pragma unroll
            for (int i = 0; i < 4; i++) {
                int r = m_off + i*16 + lane4;
                a[i][0] = As[r][kk];   a[i][1] = As[r+8][kk];
                a[i][2] = As[r][kk+4]; a[i][3] = As[r+8][kk+4];
            }
            #pragma unroll
            for (int j = 0; j < 4; j++) {
                int r = n_off + j*8 + lane4;
                b[j][0] = Bs[r][kk];  b[j][1] = Bs[r][kk+4];
            }
            #pragma unroll
            for (int i = 0; i < 4; i++)
                #pragma unroll
                for (int j = 0; j < 4; j++) mma_tf32(c[i][j], a[i], b[j]);
        }
        __syncthreads();
        if (more) {
            uint4 ua0 = make_uint4(f2tf(apf[0].x), f2tf(apf[0].y), f2tf(apf[0].z), f2tf(apf[0].w));
            uint4 ua1 = make_uint4(f2tf(apf[1].x), f2tf(apf[1].y), f2tf(apf[1].z), f2tf(apf[1].w));
            uint4 ub0 = make_uint4(f2tf(bpf[0].x), f2tf(bpf[0].y), f2tf(bpf[0].z), f2tf(bpf[0].w));
            uint4 ub1 = make_uint4(f2tf(bpf[1].x), f2tf(bpf[1].y), f2tf(bpf[1].z), f2tf(bpf[1].w));
            *(uint4*)&As[srow0][skg] = ua0; *(uint4*)&As[srow1][skg] = ua1;
            *(uint4*)&Bs[srow0][skg] = ub0; *(uint4*)&Bs[srow1][skg] = ub1;
        }
        __syncthreads();
    }

    #pragma unroll
    for (int i = 0; i < 4; i++) {
        int row = m0 + m_off + i*16 + lane4;
        #pragma unroll
        for (int j = 0; j < 4; j++) {
            int col = n0 + n_off + j*8 + lanem*2;
            float bv0 = bb ? bb[col] : 0.f;
            float bv1 = bb ? bb[col+1] : 0.f;
            float2 lo = make_float2(c[i][j][0] + bv0, c[i][j][1] + bv1);
            float2 hi = make_float2(c[i][j][2] + bv0, c[i][j][3] + bv1);
            *(float2*)(Cb + (long)row*ldc + col)     = lo;
            *(float2*)(Cb + (long)(row+8)*ldc + col) = hi;
        }
    }
}

// =========================================================================================
// tf32 tensor-core NN GEMM: C[m,n] = sum_k A[m,k]*B[k,n]. A row-major MxK, B row-major KxN.
// M,N multiples of 128; K multiple of 16. Batched over z.
// If lens != nullptr: truncate K to ceil(lens[z]/16)*16 (A columns beyond are exactly 0).
// =========================================================================================
__launch_bounds__(256)
__global__ void tgemm_nn(const float* __restrict__ A, int lda, long sA,
                         const float* __restrict__ B, int ldb, long sB,
                         float* __restrict__ C, int ldc, long sC,
                         int K, const int* __restrict__ lens) {
    __shared__ unsigned As[128][20];
    __shared__ unsigned Bs[16][136];   // [k][n] stride 136: conflict-free b-frag loads
    int z = blockIdx.z;
    int Keff = K;
    if (lens) {
        int L = lens[z];
        Keff = (L + 15) & ~15;
        if (Keff > K) Keff = K;
        if (Keff < 16) Keff = 16;
    }
    const float* Ab = A + (long)z*sA;
    const float* Bb = B + (long)z*sB;
    float* Cb = C + (long)z*sC;
    int m0 = blockIdx.y*128, n0 = blockIdx.x*128;
    int t = threadIdx.x;
    int lane = t & 31, wid = t >> 5;
    int m_off = (wid & 1)*64, n_off = (wid >> 1)*32;
    int lane4 = lane >> 2, lanem = lane & 3;

    float c[4][4][4];
    #pragma unroll
    for (int i = 0; i < 4; i++)
        #pragma unroll
        for (int j = 0; j < 4; j++)
            #pragma unroll
            for (int q = 0; q < 4; q++) c[i][j][q] = 0.f;

    int arow0 = t >> 2, arow1 = 64 + (t >> 2);
    int akg = (t & 3)*4;
    int bk0 = t >> 5, bk1 = 8 + (t >> 5);
    int bn = (t & 31)*4;
    float4 apf[2], bpf[2];

    apf[0] = *(const float4*)(Ab + (long)(m0+arow0)*lda + akg);
    apf[1] = *(const float4*)(Ab + (long)(m0+arow1)*lda + akg);
    bpf[0] = *(const float4*)(Bb + (long)bk0*ldb + n0 + bn);
    bpf[1] = *(const float4*)(Bb + (long)bk1*ldb + n0 + bn);
    {
        uint4 ua0 = make_uint4(f2tf(apf[0].x), f2tf(apf[0].y), f2tf(apf[0].z), f2tf(apf[0].w));
        uint4 ua1 = make_uint4(f2tf(apf[1].x), f2tf(apf[1].y), f2tf(apf[1].z), f2tf(apf[1].w));
        uint4 ub0 = make_uint4(f2tf(bpf[0].x), f2tf(bpf[0].y), f2tf(bpf[0].z), f2tf(bpf[0].w));
        uint4 ub1 = make_uint4(f2tf(bpf[1].x), f2tf(bpf[1].y), f2tf(bpf[1].z), f2tf(bpf[1].w));
        *(uint4*)&As[arow0][akg] = ua0; *(uint4*)&As[arow1][akg] = ua1;
        *(uint4*)&Bs[bk0][bn] = ub0;    *(uint4*)&Bs[bk1][bn] = ub1;
    }
    __syncthreads();

    int niter = Keff >> 4;
    for (int it = 0; it < niter; it++) {
        bool more = (it + 1 < niter);
        if (more) {
            int k0 = (it+1) << 4;
            apf[0] = *(const float4*)(Ab + (long)(m0+arow0)*lda + k0 + akg);
            apf[1] = *(const float4*)(Ab + (long)(m0+arow1)*lda + k0 + akg);
            bpf[0] = *(const float4*)(Bb + (long)(k0+bk0)*ldb + n0 + bn);
            bpf[1] = *(const float4*)(Bb + (long)(k0+bk1)*ldb + n0 + bn);
        }
        #pragma unroll
        for (int ks = 0; ks < 2; ks++) {
            int kk = ks*8 + lanem;
            unsigned a[4][4], b[4][2];
            #pragma unroll
            for (int i = 0; i < 4; i++) {
                int r = m_off + i*16 + lane4;
                a[i][0] = As[r][kk];   a[i][1] = As[r+8][kk];
                a[i][2] = As[r][kk+4]; a[i][3] = As[r+8][kk+4];
            }
            #pragma unroll
            for (int j = 0; j < 4; j++) {
                int col = n_off + j*8 + lane4;
                b[j][0] = Bs[kk][col];  b[j][1] = Bs[kk+4][col];
            }
            #pragma unroll
            for (int i = 0; i < 4; i++)
                #pragma unroll
                for (int j = 0; j < 4; j++) mma_tf32(c[i][j], a[i], b[j]);
        }
        __syncthreads();
        if (more) {
            uint4 ua0 = make_uint4(f2tf(apf[0].x), f2tf(apf[0].y), f2tf(apf[0].z), f2tf(apf[0].w));
            uint4 ua1 = make_uint4(f2tf(apf[1].x), f2tf(apf[1].y), f2tf(apf[1].z), f2tf(apf[1].w));
            uint4 ub0 = make_uint4(f2tf(bpf[0].x), f2tf(bpf[0].y), f2tf(bpf[0].z), f2tf(bpf[0].w));
            uint4 ub1 = make_uint4(f2tf(bpf[1].x), f2tf(bpf[1].y), f2tf(bpf[1].z), f2tf(bpf[1].w));
            *(uint4*)&As[arow0][akg] = ua0; *(uint4*)&As[arow1][akg] = ua1;
            *(uint4*)&Bs[bk0][bn] = ub0;    *(uint4*)&Bs[bk1][bn] = ub1;
        }
        __syncthreads();
    }

    #pragma unroll
    for (int i = 0; i < 4; i++) {
        int row = m0 + m_off + i*16 + lane4;
        #pragma unroll
        for (int j = 0; j < 4; j++) {
            int col = n0 + n_off + j*8 + lanem*2;
            float2 lo = make_float2(c[i][j][0], c[i][j][1]);
            float2 hi = make_float2(c[i][j][2], c[i][j][3]);
            *(float2*)(Cb + (long)row*ldc + col)     = lo;
            *(float2*)(Cb + (long)(row+8)*ldc + col) = hi;
        }
    }
}

// ---------------- fp32 NT SGEMM (kept for small pooled stage, split-K) ----------------
__launch_bounds__(256, 2)
__global__ void sgemm_nt(const float* __restrict__ A, int lda,
                         const float* __restrict__ B, int ldb,
                         float* __restrict__ C, int ldc, long sCk,
                         int M, int N, int K, int ksplit) {
    __shared__ float As[8][128];
    __shared__ float Bs[8][128];
    int kc = blockIdx.z;
    float* Cb = C + (long)kc*sCk;
    int Kc = K / ksplit, kbeg = kc*Kc, kend = kbeg + Kc;

    int tid = threadIdx.x;
    int tm = tid >> 4, tn = tid & 15;
    int m0 = blockIdx.y*128, n0 = blockIdx.x*128;
    int ar = tid >> 1, ac = (tid & 1)*4;

    float acc[8][8];
    #pragma unroll
    for (int i = 0; i < 8; i++)
        #pragma unroll
        for (int j = 0; j < 8; j++) acc[i][j] = 0.f;

    const float* Aptr = A + (long)(m0+ar)*lda;
    const float* Bptr = B + (long)(n0+ar)*ldb;
    bool am = (m0 + ar) < M, bn = (n0 + ar) < N;

    for (int k0 = kbeg; k0 < kend; k0 += 8) {
        float4 av = make_float4(0,0,0,0), bv = make_float4(0,0,0,0);
        if (am) av = *(const float4*)(Aptr + k0 + ac);
        if (bn) bv = *(const float4*)(Bptr + k0 + ac);
        __syncthreads();
        As[ac+0][ar] = av.x; As[ac+1][ar] = av.y; As[ac+2][ar] = av.z; As[ac+3][ar] = av.w;
        Bs[ac+0][ar] = bv.x; Bs[ac+1][ar] = bv.y; Bs[ac+2][ar] = bv.z; Bs[ac+3][ar] = bv.w;
        __syncthreads();
        #pragma unroll
        for (int k = 0; k < 8; k++) {
            float4 a0 = *(const float4*)&As[k][tm*8];
            float4 a1 = *(const float4*)&As[k][tm*8+4];
            float4 b0 = *(const float4*)&Bs[k][tn*8];
            float4 b1 = *(const float4*)&Bs[k][tn*8+4];
            float ra[8] = {a0.x,a0.y,a0.z,a0.w,a1.x,a1.y,a1.z,a1.w};
            float rb[8] = {b0.x,b0.y,b0.z,b0.w,b1.x,b1.y,b1.z,b1.w};
            #pragma unroll
            for (int i = 0; i < 8; i++)
                #pragma unroll
                for (int j = 0; j < 8; j++) acc[i][j] += ra[i]*rb[j];
        }
    }
    #pragma unroll
    for (int i = 0; i < 8; i++) {
        int m = m0 + tm*8 + i;
        if (m >= M) continue;
        #pragma unroll
        for (int j = 0; j < 8; j++) {
            int n = n0 + tn*8 + j;
            if (n < N) Cb[(long)m*ldc + n] = acc[i][j];
        }
    }
}

// ---------------- masked softmax over s (attn in place; writes only s < ceil16(L)) ------
__global__ void k_softmax() {
    int row = blockIdx.x;          // b*128 + hp
    int b = row >> 7;
    int L = g_len[b];
    int Lk = (L + 15) & ~15;       // Y-GEMM K bound; nothing beyond is ever read
    float* r = g_scores + (long)row*S_;
    int t = threadIdx.x;
    float v[8];
    float mx = -1e30f;
    #pragma unroll
    for (int i = 0; i < 8; i++) {
        int s = t + i*256;
        v[i] = (s < L) ? r[s] : -1e30f;
        mx = fmaxf(mx, v[i]);
    }
    __shared__ float sh[256];
    sh[t] = mx; __syncthreads();
    for (int o = 128; o > 0; o >>= 1) { if (t < o) sh[t] = fmaxf(sh[t], sh[t+o]); __syncthreads(); }
    mx = sh[0]; __syncthreads();
    float sum = 0.f;
    #pragma unroll
    for (int i = 0; i < 8; i++) {
        int s = t + i*256;
        if (s < L) { v[i] = expf(v[i]-mx); sum += v[i]; } else v[i] = 0.f;
    }
    sh[t] = sum; __syncthreads();
    for (int o = 128; o > 0; o >>= 1) { if (t < o) sh[t] += sh[t+o]; __syncthreads(); }
    float tot = sh[0];
    float inv = (tot > 0.f) ? (1.f / tot) : 0.f;   // NaN guard
    #pragma unroll
    for (int i = 0; i < 8; i++) {
        int s = t + i*256;
        if (s < Lk) r[s] = v[i]*inv;
    }
}

// ---------------- ctx[b,p,h*64+j] = Y[b,h*8+p,:] . Wv[h*64+j,:] + bv ----------------
__global__ void k_ctx(const float* __restrict__ W, const float* __restrict__ bias) {
    int h = blockIdx.x, b = blockIdx.y;
    __shared__ float As[8][33];
    __shared__ float Bs[64][33];
    int tid = threadIdx.x;
    int lr = tid >> 5, lc = tid & 31;
    const float* Yb = g_Y + ((long)b*128 + h*8)*D_;
    const float* Wb = W + (2L*D_ + h*64)*D_;
    float acc0 = 0.f, acc1 = 0.f;
    int p0 = tid >> 6, j0 = tid & 63;
    for (int k0 = 0; k0 < D_; k0 += 32) {
        __syncthreads();
        As[lr][lc] = Yb[(long)lr*D_ + k0 + lc];
        #pragma unroll
        for (int i = 0; i < 8; i++)
            Bs[i*8+lr][lc] = Wb[(long)(i*8+lr)*D_ + k0 + lc];
        __syncthreads();
        #pragma unroll
        for (int k = 0; k < 32; k++) {
            float bb = Bs[j0][k];
            acc0 += As[p0][k]*bb;
            acc1 += As[p0+4][k]*bb;
        }
    }
    float bj = bias[2L*D_ + h*64 + j0];
    g_ctx[((long)b*P_ + p0  )*D_ + h*64 + j0] = acc0 + bj;
    g_ctx[((long)b*P_ + p0+4)*D_ + h*64 + j0] = acc1 + bj;
}

// ---------------- pma rows: LN(queries + pooled(reduced) + out_b) -> summary[1..8] ----------------
__global__ void k_pma_ln(const float* __restrict__ queries, const float* __restrict__ outb,
                         const float* __restrict__ g, const float* __restrict__ bt) {
    int blk = blockIdx.x;  // 0..127
    int b = blk >> 3, p = blk & 7;
    int t = threadIdx.x;
    float x[4];
    float s1 = 0.f, s2 = 0.f;
    #pragma unroll
    for (int i = 0; i < 4; i++) {
        int d = t + i*256;
        float v = queries[(long)p*D_ + d] + outb[d];
        #pragma unroll
        for (int kc = 0; kc < KSPLIT_POOL; kc++)
            v += g_pooled[((long)kc*B_*P_ + (long)b*P_ + p)*D_ + d];
        x[i] = v; s1 += v; s2 += v*v;
    }
    __shared__ float sh1[256], sh2[256];
    sh1[t] = s1; sh2[t] = s2; __syncthreads();
    for (int o = 128; o > 0; o >>= 1) { if (t < o) { sh1[t]+=sh1[t+o]; sh2[t]+=sh2[t+o]; } __syncthreads(); }
    float mu = sh1[0]/D_;
    float var = sh2[0]/D_ - mu*mu;
    float rs = rsqrtf(var + 1e-5f);
    #pragma unroll
    for (int i = 0; i < 4; i++) {
        int d = t + i*256;
        g_summary[((long)b*NSUM + 1 + p)*D_ + d] = (x[i]-mu)*rs*g[d] + bt[d];
    }
}

// ---------------- cls + recent gather + mask flags ----------------
__global__ void k_summary(const float* __restrict__ X) {
    int t = blockIdx.x;   // 0..64
    int b = blockIdx.y;
    int L = g_len[b];
    int tid = threadIdx.x;
    if (t == 0) {
        const float* src = X + (long)b*S_*D_;
        float* dst = g_summary + (long)b*NSUM*D_;
        #pragma unroll
        for (int i = 0; i < 4; i++) { int d = tid + i*256; dst[d] = src[d]; }
        if (tid == 0) g_maskf[b*NSUM] = (L > 0) ? 1.f : 0.f;
        if (tid >= 1 && tid <= 8) g_maskf[b*NSUM + tid] = 1.f;  // pma always valid
    } else {
        int j = t - 1;
        int s = L - R_ + j;                        // original sequence index
        int valid = (s >= 1) && (L >= 1);          // token must come from X[:,1:]
        float* dst = g_summary + ((long)b*NSUM + 9 + j)*D_;
        if (valid) {
            const float* src = X + ((long)b*S_ + s)*D_;
            #pragma unroll
            for (int i = 0; i < 4; i++) { int d = tid + i*256; dst[d] = src[d]; }
        } else {
            #pragma unroll
            for (int i = 0; i < 4; i++) { int d = tid + i*256; dst[d] = 0.f; }
        }
        if (tid == 0) g_maskf[b*NSUM + 9 + j] = valid ? 1.f : 0.f;
    }
}

// ---------------- two LN variants of each summary row -> g_norm sections ----------------
__global__ void k_norm2(const float* __restrict__ gv, const float* __restrict__ bv,
                        const float* __restrict__ gg, const float* __restrict__ bg) {
    int r = blockIdx.x;   // 0..1167
    int t = threadIdx.x;
    const float* xr = g_summary + (long)r*D_;
    float x[4];
    float s1 = 0.f, s2 = 0.f;
    #pragma unroll
    for (int i = 0; i < 4; i++) {
        int d = t + i*256;
        float v = xr[d];
        x[i] = v; s1 += v; s2 += v*v;
    }
    __shared__ float sh1[256], sh2[256];
    sh1[t] = s1; sh2[t] = s2; __syncthreads();
    for (int o = 128; o > 0; o >>= 1) { if (t < o) { sh1[t]+=sh1[t+o]; sh2[t]+=sh2[t+o]; } __syncthreads(); }
    float mu = sh1[0]/D_;
    float var = sh2[0]/D_ - mu*mu;
    float rs = rsqrtf(fmaxf(var, 0.f) + 1e-5f);
    #pragma unroll
    for (int i = 0; i < 4; i++) {
        int d = t + i*256;
        float xn = (x[i]-mu)*rs;
        g_norm[(long)r*D_ + d]                 = xn*gv[d] + bv[d];
        g_norm[(long)MPAD*D_ + (long)r*D_ + d] = xn*gg[d] + bg[d];
    }
}

// ---------------- epilogue: gated = sigmoid(gate)*silu(val)*mask ; write d_out ----------------
__global__ void k_out(float* __restrict__ out, long out_size) {
    long idx = (long)blockIdx.x*256 + threadIdx.x;
    if (idx >= out_size) return;
    const long NG = (long)NROWS*D_;
    if (idx < NG) {
        long r = idx >> 10;
        int d = (int)(idx & 1023);
        float vp = g_valgate[r*D_ + d];
        float gp = g_valgate[(long)MPAD*D_ + r*D_ + d];
        float sv = 1.f/(1.f + expf(-vp));
        float sg = 1.f/(1.f + expf(-gp));
        out[idx] = sg * (vp*sv) * g_maskf[r];
    } else {
        long mi = idx - NG;
        out[idx] = (mi < NROWS) ? g_maskf[mi] : 0.f;
    }
}

// =========================================================================================
extern "C" void kernel_launch(void* const* d_in, const int* in_sizes, int n_in,
                              void* d_out, int out_size) {
    const float*         X        = (const float*)d_in[0];
    const void*          vmask    = (const void*)d_in[1];
    const float*         queries  = (const float*)d_in[2];
    const float*         in_w     = (const float*)d_in[3];
    const float*         in_b     = (const float*)d_in[4];
    const float*         out_w    = (const float*)d_in[5];
    const float*         out_b    = (const float*)d_in[6];
    const float*         ln_pma_g = (const float*)d_in[7];
    const float*         ln_pma_b = (const float*)d_in[8];
    const float*         ln_v_g   = (const float*)d_in[9];
    const float*         ln_v_b   = (const float*)d_in[10];
    const float*         W_v      = (const float*)d_in[11];
    const float*         b_v      = (const float*)d_in[12];
    const float*         ln_g_g   = (const float*)d_in[13];
    const float*         ln_g_b   = (const float*)d_in[14];
    const float*         W_g      = (const float*)d_in[15];
    const float*         b_g      = (const float*)d_in[16];

    float *p_qt, *p_scores, *p_Y, *p_ctx, *p_pooled, *p_norm, *p_valgate;
    int   *p_len;
    cudaGetSymbolAddress((void**)&p_qt,      g_qt);
    cudaGetSymbolAddress((void**)&p_scores,  g_scores);
    cudaGetSymbolAddress((void**)&p_Y,       g_Y);
    cudaGetSymbolAddress((void**)&p_ctx,     g_ctx);
    cudaGetSymbolAddress((void**)&p_pooled,  g_pooled);
    cudaGetSymbolAddress((void**)&p_norm,    g_norm);
    cudaGetSymbolAddress((void**)&p_valgate, g_valgate);
    cudaGetSymbolAddress((void**)&p_len,     g_len);

    // lengths (mode detection folded in)
    k_len<<<B_, 256>>>(vmask);
    // q = queries @ Wq^T + bq
    k_q<<<(P_*D_*32)/256, 256>>>(queries, in_w, in_b);
    // q~ (folds 1/sqrt(hd); bk dropped: softmax-invariant)
    k_qt<<<(128*D_)/256, 256>>>(in_w);
    // scores[b,hp,s] = q~[hp,:] . X[b,s,:]   — tf32 tensor cores, dead columns skipped
    tgemm_nt<<<dim3(S_/128, 1, B_), 256>>>(
        p_qt, D_, 0L,
        X, D_, (long)S_*D_, nullptr,
        p_scores, S_, 128L*S_,
        nullptr, nullptr, D_, p_len);
    // masked softmax (attn; zeros through ceil16(L))
    k_softmax<<<B_*128, 256>>>();
    // Y[b,hp,:] = attn[b,hp,:] @ X[b]       — tf32 tensor cores, K truncated to ceil16(L)
    tgemm_nn<<<dim3(D_/128, 1, B_), 256>>>(
        p_scores, S_, 128L*S_,
        X, D_, (long)S_*D_,
        p_Y, D_, 128L*D_,
        S_, p_len);
    // ctx = per-head Y @ Wv_h^T + bv
    k_ctx<<<dim3(H_, B_), 256>>>(in_w, in_b);
    // pooled = ctx @ out_w^T  (split-K fp32 partials, reduced in k_pma_ln)
    sgemm_nt<<<dim3(D_/128, 1, KSPLIT_POOL), 256>>>(
        p_ctx, D_, out_w, D_,
        p_pooled, D_, (long)B_*P_*D_,
        B_*P_, D_, D_, KSPLIT_POOL);
    // pma tokens = LN(queries + pooled + out_b)
    k_pma_ln<<<B_*P_, 256>>>(queries, out_b, ln_pma_g, ln_pma_b);
    // cls + recent gather + masks
    k_summary<<<dim3(1 + R_, B_), 256>>>(X);
    // LN_v and LN_g of all summary rows
    k_norm2<<<NROWS, 256>>>(ln_v_g, ln_v_b, ln_g_g, ln_g_b);
    // val/gate dual GEMM — tf32 tensor cores (z=0: W_v,b_v; z=1: W_g,b_g)
    tgemm_nt<<<dim3(D_/128, MPAD/128, 2), 256>>>(
        p_norm, D_, (long)MPAD*D_,
        W_v, D_, 0L, W_g,
        p_valgate, D_, (long)MPAD*D_,
        b_v, b_g, D_, nullptr);
    // epilogue + mask tail (covers every d_out element; poison-safe)
    long osz = (long)out_size;
    long nblk = (osz + 255) / 256;
    k_out<<<(unsigned)nblk, 256>>>((float*)d_out, osz);
}

// round 9
// speedup vs baseline: 3.1304x; 1.2365x over previous
#include <cuda_runtime.h>
#include <math.h>

// Problem constants (fixed by setup_inputs)
#define B_    16
#define S_    2048
#define D_    1024
#define H_    16
#define P_    8
#define R_    64
#define NSUM  73                  // 1 cls + 8 pma + 64 recent
#define NROWS (B_*NSUM)           // 1168
#define MPAD  1280                // padded row count for stage-G GEMM
#define KSPLIT_POOL 4

// ---------------- scratch (device globals; zero-initialized at load) ----------------
__device__ float g_q[P_*D_];
__device__ float g_qt[128*D_];
__device__ float g_scores[2L*B_*128*S_];             // 2 split-K partials; [0] becomes attn
__device__ float g_Y[2L*B_*128*D_];                  // 2 split-K partials
__device__ float g_ctx[(long)B_*P_*D_];
__device__ float g_pooled[(long)KSPLIT_POOL*B_*P_*D_]; // split-K partials (no atomics)
__device__ float g_summary[(long)NROWS*D_];
__device__ float g_norm[2L*MPAD*D_];                 // [0]=LN_v rows, [1]=LN_g rows
__device__ float g_valgate[4L*MPAD*D_];              // [kc][val/gate] partials
__device__ float g_maskf[NROWS];
__device__ int   g_len[B_];

// ---------------- tf32 helpers ----------------
__device__ __forceinline__ unsigned f2tf(float x) {
    unsigned u; asm("cvt.rna.tf32.f32 %0, %1;" : "=r"(u) : "f"(x)); return u;
}
__device__ __forceinline__ void mma_tf32(float c[4], const unsigned a[4], const unsigned b[2]) {
    asm volatile("mma.sync.aligned.m16n8k8.row.col.f32.tf32.tf32.f32 "
        "{%0,%1,%2,%3}, {%4,%5,%6,%7}, {%8,%9}, {%0,%1,%2,%3};"
        : "+f"(c[0]), "+f"(c[1]), "+f"(c[2]), "+f"(c[3])
        : "r"(a[0]), "r"(a[1]), "r"(a[2]), "r"(a[3]), "r"(b[0]), "r"(b[1]));
}

// ---------------- lengths from valid_mask (dtype-adaptive; mode detected in-block) ----
__global__ void k_len(const void* __restrict__ mask) {
    int b = blockIdx.x, t = threadIdx.x;
    const int* mi = (const int*)mask;
    int w0 = mi[0], w1 = mi[1], w2 = mi[2], w3 = mi[3];
    int mode = ((unsigned)w0 <= 1u) & ((unsigned)w1 <= 1u) &
               ((unsigned)w2 <= 1u) & ((unsigned)w3 <= 1u);
    int s = 0;
    if (mode) {
        const int* m = (const int*)mask;
        for (int i = t; i < S_; i += 256) s += (m[(long)b*S_ + i] != 0) ? 1 : 0;
    } else {
        const unsigned char* m = (const unsigned char*)mask;
        for (int i = t; i < S_; i += 256) s += m[(long)b*S_ + i] ? 1 : 0;
    }
    __shared__ int sh[256];
    sh[t] = s; __syncthreads();
    for (int o = 128; o > 0; o >>= 1) { if (t < o) sh[t] += sh[t+o]; __syncthreads(); }
    if (t == 0) g_len[b] = sh[0];
}

// ---------------- q = queries @ Wq^T + bq  (warp per output) ----------------
__global__ void k_q(const float* __restrict__ queries, const float* __restrict__ W,
                    const float* __restrict__ bias) {
    int w = (blockIdx.x*blockDim.x + threadIdx.x) >> 5;
    int lane = threadIdx.x & 31;
    if (w >= P_*D_) return;
    int p = w / D_, d = w % D_;
    const float* qr = queries + (long)p*D_;
    const float* wr = W + (long)d*D_;
    float acc = 0.f;
    for (int k = lane; k < D_; k += 32) acc += qr[k]*wr[k];
    for (int o = 16; o > 0; o >>= 1) acc += __shfl_down_sync(0xffffffffu, acc, o);
    if (lane == 0) g_q[(long)p*D_ + d] = acc + bias[d];
}

// ---------------- qt[hp,d] = (1/8) * sum_j q[p, h*64+j] * Wk[h*64+j, d] ----------------
__global__ void k_qt(const float* __restrict__ W) {
    int idx = blockIdx.x*blockDim.x + threadIdx.x;   // 131072
    int hp = idx >> 10, d = idx & 1023;
    int h = hp >> 3, p = hp & 7;
    const float* qrow = g_q + (long)p*D_ + h*64;
    const float* wb   = W + ((long)D_ + h*64)*D_ + d;
    float acc = 0.f;
    #pragma unroll 8
    for (int j = 0; j < 64; j++) acc += qrow[j]*wb[(long)j*D_];
    g_qt[idx] = acc * 0.125f;
}

// =========================================================================================
// tf32 NT GEMM, 2-stage double-buffered, optional split-K (ksplit in {1,2}).
// C[m,n] = sum_k A[m,k]*B[n,k] (+bias on kc==0). z = batch*ksplit + kc.
// If batch==1 && B1: use B1/bias1. If lens: skip block when n0 >= lens[batch].
// M,N multiples of 128; K/ksplit multiple of 16.
// =========================================================================================
__launch_bounds__(256, 2)
__global__ void tgemm_nt(const float* __restrict__ A, int lda, long sA,
                         const float* __restrict__ B, int ldb, long sB,
                         const float* __restrict__ B1,
                         float* __restrict__ C, int ldc, long sC, long sCk,
                         const float* __restrict__ bias, const float* __restrict__ bias1,
                         int K, int ksplit, const int* __restrict__ lens) {
    __shared__ unsigned As[2][128][20];
    __shared__ unsigned Bs[2][128][20];
    int z = blockIdx.z;
    int batch = z / ksplit, kc = z - batch*ksplit;
    int m0 = blockIdx.y*128, n0 = blockIdx.x*128;
    if (lens && n0 >= lens[batch]) return;       // dead score columns: exact skip
    const float* Ab = A + (long)batch*sA;
    const float* Bb = B + (long)batch*sB;
    const float* bb = (kc == 0) ? bias : nullptr;
    if (batch == 1 && B1) { Bb = B1; bb = (kc == 0) ? bias1 : nullptr; }
    float* Cb = C + (long)batch*sC + (long)kc*sCk;
    int Kc = K / ksplit, kbeg = kc*Kc;

    int t = threadIdx.x;
    int lane = t & 31, wid = t >> 5;
    int m_off = (wid & 1)*64, n_off = (wid >> 1)*32;
    int lane4 = lane >> 2, lanem = lane & 3;

    float c[4][4][4];
    #pragma unroll
    for (int i = 0; i < 4; i++)
        #pragma unroll
        for (int j = 0; j < 4; j++)
            #pragma unroll
            for (int q = 0; q < 4; q++) c[i][j][q] = 0.f;

    int srow0 = t >> 2, srow1 = 64 + (t >> 2);
    int skg = (t & 3)*4;
    const float* Ap0 = Ab + (long)(m0+srow0)*lda + skg;
    const float* Ap1 = Ab + (long)(m0+srow1)*lda + skg;
    const float* Bp0 = Bb + (long)(n0+srow0)*ldb + skg;
    const float* Bp1 = Bb + (long)(n0+srow1)*ldb + skg;
    float4 apf[2], bpf[2];

    // prologue: tile kbeg -> stage 0
    apf[0] = *(const float4*)(Ap0 + kbeg);
    apf[1] = *(const float4*)(Ap1 + kbeg);
    bpf[0] = *(const float4*)(Bp0 + kbeg);
    bpf[1] = *(const float4*)(Bp1 + kbeg);
    *(uint4*)&As[0][srow0][skg] = make_uint4(f2tf(apf[0].x), f2tf(apf[0].y), f2tf(apf[0].z), f2tf(apf[0].w));
    *(uint4*)&As[0][srow1][skg] = make_uint4(f2tf(apf[1].x), f2tf(apf[1].y), f2tf(apf[1].z), f2tf(apf[1].w));
    *(uint4*)&Bs[0][srow0][skg] = make_uint4(f2tf(bpf[0].x), f2tf(bpf[0].y), f2tf(bpf[0].z), f2tf(bpf[0].w));
    *(uint4*)&Bs[0][srow1][skg] = make_uint4(f2tf(bpf[1].x), f2tf(bpf[1].y), f2tf(bpf[1].z), f2tf(bpf[1].w));
    __syncthreads();

    int niter = Kc >> 4;
    for (int it = 0; it < niter; it++) {
        int buf = it & 1;
        bool more = (it + 1 < niter);
        if (more) {
            int k0 = kbeg + ((it+1) << 4);
            apf[0] = *(const float4*)(Ap0 + k0);
            apf[1] = *(const float4*)(Ap1 + k0);
            bpf[0] = *(const float4*)(Bp0 + k0);
            bpf[1] = *(const float4*)(Bp1 + k0);
        }
        #pragma unroll
        for (int ks = 0; ks < 2; ks++) {
            int kk = ks*8 + lanem;
            unsigned a[4][4], b[4][2];
            #pragma unroll
            for (int i = 0; i < 4; i++) {
                int r = m_off + i*16 + lane4;
                a[i][0] = As[buf][r][kk];   a[i][1] = As[buf][r+8][kk];
                a[i][2] = As[buf][r][kk+4]; a[i][3] = As[buf][r+8][kk+4];
            }
            #pragma unroll
            for (int j = 0; j < 4; j++) {
                int r = n_off + j*8 + lane4;
                b[j][0] = Bs[buf][r][kk];  b[j][1] = Bs[buf][r][kk+4];
            }
            #pragma unroll
            for (int i = 0; i < 4; i++)
                #pragma unroll
                for (int j = 0; j < 4; j++) mma_tf32(c[i][j], a[i], b[j]);
        }
        if (more) {
            int nb = buf ^ 1;   // stage nb was last READ in iter it-1, fenced by that iter's barrier
            *(uint4*)&As[nb][srow0][skg] = make_uint4(f2tf(apf[0].x), f2tf(apf[0].y), f2tf(apf[0].z), f2tf(apf[0].w));
            *(uint4*)&As[nb][srow1][skg] = make_uint4(f2tf(apf[1].x), f2tf(apf[1].y), f2tf(apf[1].z), f2tf(apf[1].w));
            *(uint4*)&Bs[nb][srow0][skg] = make_uint4(f2tf(bpf[0].x), f2tf(bpf[0].y), f2tf(bpf[0].z), f2tf(bpf[0].w));
            *(uint4*)&Bs[nb][srow1][skg] = make_uint4(f2tf(bpf[1].x), f2tf(bpf[1].y), f2tf(bpf[1].z), f2tf(bpf[1].w));
        }
        __syncthreads();
    }

    #pragma unroll
    for (int i = 0; i < 4; i++) {
        int row = m0 + m_off + i*16 + lane4;
        #pragma unroll
        for (int j = 0; j < 4; j++) {
            int col = n0 + n_off + j*8 + lanem*2;
            float bv0 = bb ? bb[col] : 0.f;
            float bv1 = bb ? bb[col+1] : 0.f;
            float2 lo = make_float2(c[i][j][0] + bv0, c[i][j][1] + bv1);
            float2 hi = make_float2(c[i][j][2] + bv0, c[i][j][3] + bv1);
            *(float2*)(Cb + (long)row*ldc + col)     = lo;
            *(float2*)(Cb + (long)(row+8)*ldc + col) = hi;
        }
    }
}

// =========================================================================================
// tf32 NN GEMM, 2-stage double-buffered, optional split-K. C[m,n] = sum_k A[m,k]*B[k,n].
// z = batch*ksplit + kc. If lens: K truncated to ceil16(lens[batch]) (A cols beyond are 0),
// then split between kc=0 ([0,khalf)) and kc=1 ([khalf,Keff)).
// =========================================================================================
__launch_bounds__(256, 2)
__global__ void tgemm_nn(const float* __restrict__ A, int lda, long sA,
                         const float* __restrict__ B, int ldb, long sB,
                         float* __restrict__ C, int ldc, long sC, long sCk,
                         int K, int ksplit, const int* __restrict__ lens) {
    __shared__ unsigned As[2][128][20];
    __shared__ unsigned Bs[2][16][136];
    int z = blockIdx.z;
    int batch = z / ksplit, kc = z - batch*ksplit;
    int Keff = K;
    if (lens) {
        int L = lens[batch];
        Keff = (L + 15) & ~15;
        if (Keff > K) Keff = K;
        if (Keff < 16) Keff = 16;
    }
    int khalf = (ksplit == 2) ? (((Keff >> 1) + 15) & ~15) : Keff;
    int kbeg = kc ? khalf : 0;
    int kend = kc ? Keff  : khalf;
    int niter = (kend - kbeg) >> 4;

    const float* Ab = A + (long)batch*sA;
    const float* Bb = B + (long)batch*sB;
    float* Cb = C + (long)batch*sC + (long)kc*sCk;
    int m0 = blockIdx.y*128, n0 = blockIdx.x*128;
    int t = threadIdx.x;
    int lane = t & 31, wid = t >> 5;
    int m_off = (wid & 1)*64, n_off = (wid >> 1)*32;
    int lane4 = lane >> 2, lanem = lane & 3;

    float c[4][4][4];
    #pragma unroll
    for (int i = 0; i < 4; i++)
        #pragma unroll
        for (int j = 0; j < 4; j++)
            #pragma unroll
            for (int q = 0; q < 4; q++) c[i][j][q] = 0.f;

    int arow0 = t >> 2, arow1 = 64 + (t >> 2);
    int akg = (t & 3)*4;
    int bk0 = t >> 5, bk1 = 8 + (t >> 5);
    int bn = (t & 31)*4;

    if (niter > 0) {
        const float* Ap0 = Ab + (long)(m0+arow0)*lda + akg;
        const float* Ap1 = Ab + (long)(m0+arow1)*lda + akg;
        float4 apf[2], bpf[2];
        apf[0] = *(const float4*)(Ap0 + kbeg);
        apf[1] = *(const float4*)(Ap1 + kbeg);
        bpf[0] = *(const float4*)(Bb + (long)(kbeg+bk0)*ldb + n0 + bn);
        bpf[1] = *(const float4*)(Bb + (long)(kbeg+bk1)*ldb + n0 + bn);
        *(uint4*)&As[0][arow0][akg] = make_uint4(f2tf(apf[0].x), f2tf(apf[0].y), f2tf(apf[0].z), f2tf(apf[0].w));
        *(uint4*)&As[0][arow1][akg] = make_uint4(f2tf(apf[1].x), f2tf(apf[1].y), f2tf(apf[1].z), f2tf(apf[1].w));
        *(uint4*)&Bs[0][bk0][bn]    = make_uint4(f2tf(bpf[0].x), f2tf(bpf[0].y), f2tf(bpf[0].z), f2tf(bpf[0].w));
        *(uint4*)&Bs[0][bk1][bn]    = make_uint4(f2tf(bpf[1].x), f2tf(bpf[1].y), f2tf(bpf[1].z), f2tf(bpf[1].w));
        __syncthreads();

        for (int it = 0; it < niter; it++) {
            int buf = it & 1;
            bool more = (it + 1 < niter);
            if (more) {
                int k0 = kbeg + ((it+1) << 4);
                apf[0] = *(const float4*)(Ap0 + k0);
                apf[1] = *(const float4*)(Ap1 + k0);
                bpf[0] = *(const float4*)(Bb + (long)(k0+bk0)*ldb + n0 + bn);
                bpf[1] = *(const float4*)(Bb + (long)(k0+bk1)*ldb + n0 + bn);
            }
            #pragma unroll
            for (int ks = 0; ks < 2; ks++) {
                int kk = ks*8 + lanem;
                unsigned a[4][4], b[4][2];
                #pragma unroll
                for (int i = 0; i < 4; i++) {
                    int r = m_off + i*16 + lane4;
                    a[i][0] = As[buf][r][kk];   a[i][1] = As[buf][r+8][kk];
                    a[i][2] = As[buf][r][kk+4]; a[i][3] = As[buf][r+8][kk+4];
                }
                #pragma unroll
                for (int j = 0; j < 4; j++) {
                    int col = n_off + j*8 + lane4;
                    b[j][0] = Bs[buf][kk][col];  b[j][1] = Bs[buf][kk+4][col];
                }
                #pragma unroll
                for (int i = 0; i < 4; i++)
                    #pragma unroll
                    for (int j = 0; j < 4; j++) mma_tf32(c[i][j], a[i], b[j]);
            }
            if (more) {
                int nb = buf ^ 1;
                *(uint4*)&As[nb][arow0][akg] = make_uint4(f2tf(apf[0].x), f2tf(apf[0].y), f2tf(apf[0].z), f2tf(apf[0].w));
                *(uint4*)&As[nb][arow1][akg] = make_uint4(f2tf(apf[1].x), f2tf(apf[1].y), f2tf(apf[1].z), f2tf(apf[1].w));
                *(uint4*)&Bs[nb][bk0][bn]    = make_uint4(f2tf(bpf[0].x), f2tf(bpf[0].y), f2tf(bpf[0].z), f2tf(bpf[0].w));
                *(uint4*)&Bs[nb][bk1][bn]    = make_uint4(f2tf(bpf[1].x), f2tf(bpf[1].y), f2tf(bpf[1].z), f2tf(bpf[1].w));
            }
            __syncthreads();
        }
    }

    #pragma unroll
    for (int i = 0; i < 4; i++) {
        int row = m0 + m_off + i*16 + lane4;
        #pragma unroll
        for (int j = 0; j < 4; j++) {
            int col = n0 + n_off + j*8 + lanem*2;
            float2 lo = make_float2(c[i][j][0], c[i][j][1]);
            float2 hi = make_float2(c[i][j][2], c[i][j][3]);
            *(float2*)(Cb + (long)row*ldc + col)     = lo;
            *(float2*)(Cb + (long)(row+8)*ldc + col) = hi;
        }
    }
}

// ---------------- fp32 NT SGEMM (kept for small pooled stage, split-K) ----------------
__launch_bounds__(256, 2)
__global__ void sgemm_nt(const float* __restrict__ A, int lda,
                         const float* __restrict__ B, int ldb,
                         float* __restrict__ C, int ldc, long sCk,
                         int M, int N, int K, int ksplit) {
    __shared__ float As[8][128];
    __shared__ float Bs[8][128];
    int kc = blockIdx.z;
    float* Cb = C + (long)kc*sCk;
    int Kc = K / ksplit, kbeg = kc*Kc, kend = kbeg + Kc;

    int tid = threadIdx.x;
    int tm = tid >> 4, tn = tid & 15;
    int m0 = blockIdx.y*128, n0 = blockIdx.x*128;
    int ar = tid >> 1, ac = (tid & 1)*4;

    float acc[8][8];
    #pragma unroll
    for (int i = 0; i < 8; i++)
        #pragma unroll
        for (int j = 0; j < 8; j++) acc[i][j] = 0.f;

    const float* Aptr = A + (long)(m0+ar)*lda;
    const float* Bptr = B + (long)(n0+ar)*ldb;
    bool am = (m0 + ar) < M, bn = (n0 + ar) < N;

    for (int k0 = kbeg; k0 < kend; k0 += 8) {
        float4 av = make_float4(0,0,0,0), bv = make_float4(0,0,0,0);
        if (am) av = *(const float4*)(Aptr + k0 + ac);
        if (bn) bv = *(const float4*)(Bptr + k0 + ac);
        __syncthreads();
        As[ac+0][ar] = av.x; As[ac+1][ar] = av.y; As[ac+2][ar] = av.z; As[ac+3][ar] = av.w;
        Bs[ac+0][ar] = bv.x; Bs[ac+1][ar] = bv.y; Bs[ac+2][ar] = bv.z; Bs[ac+3][ar] = bv.w;
        __syncthreads();
        #pragma unroll
        for (int k = 0; k < 8; k++) {
            float4 a0 = *(const float4*)&As[k][tm*8];
            float4 a1 = *(const float4*)&As[k][tm*8+4];
            float4 b0 = *(const float4*)&Bs[k][tn*8];
            float4 b1 = *(const float4*)&Bs[k][tn*8+4];
            float ra[8] = {a0.x,a0.y,a0.z,a0.w,a1.x,a1.y,a1.z,a1.w};
            float rb[8] = {b0.x,b0.y,b0.z,b0.w,b1.x,b1.y,b1.z,b1.w};
            #pragma unroll
            for (int i = 0; i < 8; i++)
                #pragma unroll
                for (int j = 0; j < 8; j++) acc[i][j] += ra[i]*rb[j];
        }
    }
    #pragma unroll
    for (int i = 0; i < 8; i++) {
        int m = m0 + tm*8 + i;
        if (m >= M) continue;
        #pragma unroll
        for (int j = 0; j < 8; j++) {
            int n = n0 + tn*8 + j;
            if (n < N) Cb[(long)m*ldc + n] = acc[i][j];
        }
    }
}

// ---------------- masked softmax: sums 2 score partials; attn in partial 0 ----------------
__global__ void k_softmax() {
    int row = blockIdx.x;          // b*128 + hp
    int b = row >> 7;
    int L = g_len[b];
    int Lk = (L + 15) & ~15;       // Y-GEMM K bound; nothing beyond is ever read
    float* r  = g_scores + (long)row*S_;
    const float* r2 = r + (long)B_*128*S_;
    int t = threadIdx.x;
    float v[8];
    float mx = -1e30f;
    #pragma unroll
    for (int i = 0; i < 8; i++) {
        int s = t + i*256;
        v[i] = (s < L) ? (r[s] + r2[s]) : -1e30f;
        mx = fmaxf(mx, v[i]);
    }
    __shared__ float sh[256];
    sh[t] = mx; __syncthreads();
    for (int o = 128; o > 0; o >>= 1) { if (t < o) sh[t] = fmaxf(sh[t], sh[t+o]); __syncthreads(); }
    mx = sh[0]; __syncthreads();
    float sum = 0.f;
    #pragma unroll
    for (int i = 0; i < 8; i++) {
        int s = t + i*256;
        if (s < L) { v[i] = expf(v[i]-mx); sum += v[i]; } else v[i] = 0.f;
    }
    sh[t] = sum; __syncthreads();
    for (int o = 128; o > 0; o >>= 1) { if (t < o) sh[t] += sh[t+o]; __syncthreads(); }
    float tot = sh[0];
    float inv = (tot > 0.f) ? (1.f / tot) : 0.f;   // NaN guard
    #pragma unroll
    for (int i = 0; i < 8; i++) {
        int s = t + i*256;
        if (s < Lk) r[s] = v[i]*inv;
    }
}

// ---------------- ctx[b,p,h*64+j] = (Y0+Y1)[b,h*8+p,:] . Wv[h*64+j,:] + bv ----------------
__global__ void k_ctx(const float* __restrict__ W, const float* __restrict__ bias) {
    int h = blockIdx.x, b = blockIdx.y;
    __shared__ float As[8][33];
    __shared__ float Bs[64][33];
    int tid = threadIdx.x;
    int lr = tid >> 5, lc = tid & 31;
    const float* Yb  = g_Y + ((long)b*128 + h*8)*D_;
    const float* Yb2 = Yb + (long)B_*128*D_;
    const float* Wb = W + (2L*D_ + h*64)*D_;
    float acc0 = 0.f, acc1 = 0.f;
    int p0 = tid >> 6, j0 = tid & 63;
    for (int k0 = 0; k0 < D_; k0 += 32) {
        __syncthreads();
        As[lr][lc] = Yb[(long)lr*D_ + k0 + lc] + Yb2[(long)lr*D_ + k0 + lc];
        #pragma unroll
        for (int i = 0; i < 8; i++)
            Bs[i*8+lr][lc] = Wb[(long)(i*8+lr)*D_ + k0 + lc];
        __syncthreads();
        #pragma unroll
        for (int k = 0; k < 32; k++) {
            float bb = Bs[j0][k];
            acc0 += As[p0][k]*bb;
            acc1 += As[p0+4][k]*bb;
        }
    }
    float bj = bias[2L*D_ + h*64 + j0];
    g_ctx[((long)b*P_ + p0  )*D_ + h*64 + j0] = acc0 + bj;
    g_ctx[((long)b*P_ + p0+4)*D_ + h*64 + j0] = acc1 + bj;
}

// ---------------- pma rows: LN(queries + pooled(reduced) + out_b) -> summary[1..8] ----------------
__global__ void k_pma_ln(const float* __restrict__ queries, const float* __restrict__ outb,
                         const float* __restrict__ g, const float* __restrict__ bt) {
    int blk = blockIdx.x;  // 0..127
    int b = blk >> 3, p = blk & 7;
    int t = threadIdx.x;
    float x[4];
    float s1 = 0.f, s2 = 0.f;
    #pragma unroll
    for (int i = 0; i < 4; i++) {
        int d = t + i*256;
        float v = queries[(long)p*D_ + d] + outb[d];
        #pragma unroll
        for (int kc = 0; kc < KSPLIT_POOL; kc++)
            v += g_pooled[((long)kc*B_*P_ + (long)b*P_ + p)*D_ + d];
        x[i] = v; s1 += v; s2 += v*v;
    }
    __shared__ float sh1[256], sh2[256];
    sh1[t] = s1; sh2[t] = s2; __syncthreads();
    for (int o = 128; o > 0; o >>= 1) { if (t < o) { sh1[t]+=sh1[t+o]; sh2[t]+=sh2[t+o]; } __syncthreads(); }
    float mu = sh1[0]/D_;
    float var = sh2[0]/D_ - mu*mu;
    float rs = rsqrtf(var + 1e-5f);
    #pragma unroll
    for (int i = 0; i < 4; i++) {
        int d = t + i*256;
        g_summary[((long)b*NSUM + 1 + p)*D_ + d] = (x[i]-mu)*rs*g[d] + bt[d];
    }
}

// ---------------- cls + recent gather + mask flags ----------------
__global__ void k_summary(const float* __restrict__ X) {
    int t = blockIdx.x;   // 0..64
    int b = blockIdx.y;
    int L = g_len[b];
    int tid = threadIdx.x;
    if (t == 0) {
        const float* src = X + (long)b*S_*D_;
        float* dst = g_summary + (long)b*NSUM*D_;
        #pragma unroll
        for (int i = 0; i < 4; i++) { int d = tid + i*256; dst[d] = src[d]; }
        if (tid == 0) g_maskf[b*NSUM] = (L > 0) ? 1.f : 0.f;
        if (tid >= 1 && tid <= 8) g_maskf[b*NSUM + tid] = 1.f;  // pma always valid
    } else {
        int j = t - 1;
        int s = L - R_ + j;                        // original sequence index
        int valid = (s >= 1) && (L >= 1);          // token must come from X[:,1:]
        float* dst = g_summary + ((long)b*NSUM + 9 + j)*D_;
        if (valid) {
            const float* src = X + ((long)b*S_ + s)*D_;
            #pragma unroll
            for (int i = 0; i < 4; i++) { int d = tid + i*256; dst[d] = src[d]; }
        } else {
            #pragma unroll
            for (int i = 0; i < 4; i++) { int d = tid + i*256; dst[d] = 0.f; }
        }
        if (tid == 0) g_maskf[b*NSUM + 9 + j] = valid ? 1.f : 0.f;
    }
}

// ---------------- two LN variants of each summary row -> g_norm sections ----------------
__global__ void k_norm2(const float* __restrict__ gv, const float* __restrict__ bv,
                        const float* __restrict__ gg, const float* __restrict__ bg) {
    int r = blockIdx.x;   // 0..1167
    int t = threadIdx.x;
    const float* xr = g_summary + (long)r*D_;
    float x[4];
    float s1 = 0.f, s2 = 0.f;
    #pragma unroll
    for (int i = 0; i < 4; i++) {
        int d = t + i*256;
        float v = xr[d];
        x[i] = v; s1 += v; s2 += v*v;
    }
    __shared__ float sh1[256], sh2[256];
    sh1[t] = s1; sh2[t] = s2; __syncthreads();
    for (int o = 128; o > 0; o >>= 1) { if (t < o) { sh1[t]+=sh1[t+o]; sh2[t]+=sh2[t+o]; } __syncthreads(); }
    float mu = sh1[0]/D_;
    float var = sh2[0]/D_ - mu*mu;
    float rs = rsqrtf(fmaxf(var, 0.f) + 1e-5f);
    #pragma unroll
    for (int i = 0; i < 4; i++) {
        int d = t + i*256;
        float xn = (x[i]-mu)*rs;
        g_norm[(long)r*D_ + d]                 = xn*gv[d] + bv[d];
        g_norm[(long)MPAD*D_ + (long)r*D_ + d] = xn*gg[d] + bg[d];
    }
}

// ---------------- epilogue: sums 2 val/gate partials; gated = sig(gate)*silu(val)*mask ----
__global__ void k_out(float* __restrict__ out, long out_size) {
    long idx = (long)blockIdx.x*256 + threadIdx.x;
    if (idx >= out_size) return;
    const long NG = (long)NROWS*D_;
    if (idx < NG) {
        long r = idx >> 10;
        int d = (int)(idx & 1023);
        long o = r*D_ + d;
        float vp = g_valgate[o]               + g_valgate[2L*MPAD*D_ + o];
        float gp = g_valgate[(long)MPAD*D_+o] + g_valgate[3L*MPAD*D_ + o];
        float sv = 1.f/(1.f + expf(-vp));
        float sg = 1.f/(1.f + expf(-gp));
        out[idx] = sg * (vp*sv) * g_maskf[r];
    } else {
        long mi = idx - NG;
        out[idx] = (mi < NROWS) ? g_maskf[mi] : 0.f;
    }
}

// =========================================================================================
extern "C" void kernel_launch(void* const* d_in, const int* in_sizes, int n_in,
                              void* d_out, int out_size) {
    const float*         X        = (const float*)d_in[0];
    const void*          vmask    = (const void*)d_in[1];
    const float*         queries  = (const float*)d_in[2];
    const float*         in_w     = (const float*)d_in[3];
    const float*         in_b     = (const float*)d_in[4];
    const float*         out_w    = (const float*)d_in[5];
    const float*         out_b    = (const float*)d_in[6];
    const float*         ln_pma_g = (const float*)d_in[7];
    const float*         ln_pma_b = (const float*)d_in[8];
    const float*         ln_v_g   = (const float*)d_in[9];
    const float*         ln_v_b   = (const float*)d_in[10];
    const float*         W_v      = (const float*)d_in[11];
    const float*         b_v      = (const float*)d_in[12];
    const float*         ln_g_g   = (const float*)d_in[13];
    const float*         ln_g_b   = (const float*)d_in[14];
    const float*         W_g      = (const float*)d_in[15];
    const float*         b_g      = (const float*)d_in[16];

    float *p_qt, *p_scores, *p_Y, *p_ctx, *p_pooled, *p_norm, *p_valgate;
    int   *p_len;
    cudaGetSymbolAddress((void**)&p_qt,      g_qt);
    cudaGetSymbolAddress((void**)&p_scores,  g_scores);
    cudaGetSymbolAddress((void**)&p_Y,       g_Y);
    cudaGetSymbolAddress((void**)&p_ctx,     g_ctx);
    cudaGetSymbolAddress((void**)&p_pooled,  g_pooled);
    cudaGetSymbolAddress((void**)&p_norm,    g_norm);
    cudaGetSymbolAddress((void**)&p_valgate, g_valgate);
    cudaGetSymbolAddress((void**)&p_len,     g_len);

    // lengths (mode detection folded in)
    k_len<<<B_, 256>>>(vmask);
    // q = queries @ Wq^T + bq
    k_q<<<(P_*D_*32)/256, 256>>>(queries, in_w, in_b);
    // q~ (folds 1/sqrt(hd); bk dropped: softmax-invariant)
    k_qt<<<(128*D_)/256, 256>>>(in_w);
    // scores[b,hp,s] = q~[hp,:] . X[b,s,:]  — tf32, split-K=2, dead columns skipped
    tgemm_nt<<<dim3(S_/128, 1, B_*2), 256>>>(
        p_qt, D_, 0L,
        X, D_, (long)S_*D_, nullptr,
        p_scores, S_, 128L*S_, (long)B_*128*S_,
        nullptr, nullptr, D_, 2, p_len);
    // masked softmax (sums partials; attn in partial 0, zeros through ceil16(L))
    k_softmax<<<B_*128, 256>>>();
    // Y[b,hp,:] = attn[b,hp,:] @ X[b]  — tf32, split-K=2, K truncated to ceil16(L)
    tgemm_nn<<<dim3(D_/128, 1, B_*2), 256>>>(
        p_scores, S_, 128L*S_,
        X, D_, (long)S_*D_,
        p_Y, D_, 128L*D_, (long)B_*128*D_,
        S_, 2, p_len);
    // ctx = per-head (Y0+Y1) @ Wv_h^T + bv
    k_ctx<<<dim3(H_, B_), 256>>>(in_w, in_b);
    // pooled = ctx @ out_w^T  (split-K fp32 partials, reduced in k_pma_ln)
    sgemm_nt<<<dim3(D_/128, 1, KSPLIT_POOL), 256>>>(
        p_ctx, D_, out_w, D_,
        p_pooled, D_, (long)B_*P_*D_,
        B_*P_, D_, D_, KSPLIT_POOL);
    // pma tokens = LN(queries + pooled + out_b)
    k_pma_ln<<<B_*P_, 256>>>(queries, out_b, ln_pma_g, ln_pma_b);
    // cls + recent gather + masks
    k_summary<<<dim3(1 + R_, B_), 256>>>(X);
    // LN_v and LN_g of all summary rows
    k_norm2<<<NROWS, 256>>>(ln_v_g, ln_v_b, ln_g_g, ln_g_b);
    // val/gate dual GEMM — tf32, split-K=2 (batch 0: W_v,b_v; batch 1: W_g,b_g)
    tgemm_nt<<<dim3(D_/128, MPAD/128, 4), 256>>>(
        p_norm, D_, (long)MPAD*D_,
        W_v, D_, 0L, W_g,
        p_valgate, D_, (long)MPAD*D_, 2L*MPAD*D_,
        b_v, b_g, D_, 2, nullptr);
    // epilogue + mask tail (covers every d_out element; poison-safe)
    long osz = (long)out_size;
    long nblk = (osz + 255) / 256;
    k_out<<<(unsigned)nblk, 256>>>((float*)d_out, osz);
}